// round 1
// baseline (speedup 1.0000x reference)
#include <cuda_runtime.h>
#include <math.h>

#define NN 32
#define TT 243
#define VV 17
#define DD 512
#define DM 384
#define DA 128
#define NH 4
#define HD 32
#define BT (NN*TT)            // 7776 blocks
#define ROW_ELEMS (VV*DD)     // 8704 floats per (n,t) slice
#define THREADS 512

// shared memory layout (floats)
#define OFF_XS   0                       // 17*512 = 8704   original x slice (kept for residual)
#define OFF_XCN  (OFF_XS + 8704)         // 17*512 = 8704   concat output, later normalized
#define OFF_HQ   (OFF_XCN + 8704)        // 17*384 = 6528   token-mixer h, then qkv
#define OFF_XNO  (OFF_HQ + 6528)         // 17*128 = 2176   rmsnorm'd xa, then attention o
#define OFF_SC   (OFF_XNO + 2176)        // 4*17*17 = 1156  attention scores
#define OFF_H1C  (OFF_SC + 1156)         // 17*128 = 2176   MLP hidden chunk
#define OFF_W1   (OFF_H1C + 2176)        // 289
#define OFF_W2   (OFF_W1 + 289)          // 289
#define OFF_B1   (OFF_W2 + 289)          // 17
#define OFF_B2   (OFF_B1 + 17)           // 17
#define SMEM_FLOATS (OFF_B2 + 17 + 3)    // pad
#define SMEM_BYTES (SMEM_FLOATS * 4)

__device__ __forceinline__ float gelu_exact(float v) {
    return 0.5f * v * (1.0f + erff(v * 0.7071067811865475f));
}

extern "C" __global__ void __launch_bounds__(THREADS, 1)
spatial_mixer_fused(const float* __restrict__ x,
                    const float* __restrict__ tm_w1, const float* __restrict__ tm_b1,
                    const float* __restrict__ tm_w2, const float* __restrict__ tm_b2,
                    const float* __restrict__ na_w,
                    const float* __restrict__ in_w,  const float* __restrict__ in_b,
                    const float* __restrict__ out_w, const float* __restrict__ out_b,
                    const float* __restrict__ nf_w,
                    const float* __restrict__ cm_w1, const float* __restrict__ cm_b1,
                    const float* __restrict__ cm_w2, const float* __restrict__ cm_b2,
                    float* __restrict__ out)
{
    extern __shared__ float sm[];
    float* xs  = sm + OFF_XS;
    float* xcn = sm + OFF_XCN;
    float* hq  = sm + OFF_HQ;
    float* xno = sm + OFF_XNO;
    float* sc  = sm + OFF_SC;
    float* h1c = sm + OFF_H1C;
    float* w1s = sm + OFF_W1;
    float* w2s = sm + OFF_W2;
    float* b1s = sm + OFF_B1;
    float* b2s = sm + OFF_B2;

    const int tid  = threadIdx.x;
    const int warp = tid >> 5;
    const int lane = tid & 31;
    const int nwarp = THREADS >> 5;
    const size_t base = (size_t)blockIdx.x * ROW_ELEMS;
    const float* xg = x + base;

    // ---- load x slice + small token-mixer weights ----
    for (int i = tid; i < ROW_ELEMS; i += THREADS) xs[i] = xg[i];
    for (int i = tid; i < 289; i += THREADS) { w1s[i] = tm_w1[i]; w2s[i] = tm_w2[i]; }
    if (tid < 17) { b1s[tid] = tm_b1[tid]; b2s[tid] = tm_b2[tid]; }
    __syncthreads();

    // ---- token mixer stage 1: h = gelu(w1 @ xm + b1) ----
    for (int k = tid; k < VV * DM; k += THREADS) {
        int u = k / DM, d = k - u * DM;
        float acc = b1s[u];
        #pragma unroll
        for (int v = 0; v < VV; v++) acc += w1s[u * 17 + v] * xs[v * DD + d];
        hq[u * DM + d] = gelu_exact(acc);
    }
    __syncthreads();

    // ---- token mixer stage 2 -> xcn[:, :384];   rmsnorm(xa) -> xno (independent) ----
    for (int k = tid; k < VV * DM; k += THREADS) {
        int u = k / DM, d = k - u * DM;
        float acc = b2s[u];
        #pragma unroll
        for (int v = 0; v < VV; v++) acc += w2s[u * 17 + v] * hq[v * DM + d];
        xcn[u * DD + d] = acc;
    }
    for (int v = warp; v < VV; v += nwarp) {
        float s = 0.f;
        for (int d = lane; d < DA; d += 32) { float t = xs[v * DD + DM + d]; s += t * t; }
        #pragma unroll
        for (int o = 16; o; o >>= 1) s += __shfl_xor_sync(0xffffffffu, s, o);
        float r = rsqrtf(s * (1.0f / DA) + 1e-6f);
        for (int d = lane; d < DA; d += 32)
            xno[v * DA + d] = xs[v * DD + DM + d] * r * na_w[d];
    }
    __syncthreads();

    // ---- qkv = xn @ in_w.T + in_b   (overwrites hq) ----
    for (int k = tid; k < VV * 3 * DA; k += THREADS) {
        int v = k / (3 * DA), j = k - v * (3 * DA);
        const float* wr = in_w + (size_t)j * DA;
        const float* xr = xno + v * DA;
        float acc = in_b[j];
        #pragma unroll 8
        for (int d = 0; d < DA; d += 4) {
            float4 w4 = *(const float4*)(wr + d);
            float4 x4 = *(const float4*)(xr + d);
            acc += x4.x * w4.x + x4.y * w4.y + x4.z * w4.z + x4.w * w4.w;
        }
        hq[k] = acc;
    }
    __syncthreads();

    // ---- attention scores ----
    for (int k = tid; k < NH * VV * VV; k += THREADS) {
        int h = k / (VV * VV), r = k - h * VV * VV, qv = r / VV, kv = r - qv * VV;
        const float* qp = hq + qv * (3 * DA) + h * HD;
        const float* kp = hq + kv * (3 * DA) + DA + h * HD;
        float s = 0.f;
        #pragma unroll
        for (int d = 0; d < HD; d++) s += qp[d] * kp[d];
        sc[k] = s * 0.17677669529663687f;   // 1/sqrt(32)
    }
    __syncthreads();

    // ---- softmax over kv (68 rows of 17) ----
    for (int r = tid; r < NH * VV; r += THREADS) {
        float* row = sc + r * VV;
        float m = row[0];
        #pragma unroll
        for (int i = 1; i < VV; i++) m = fmaxf(m, row[i]);
        float s = 0.f;
        #pragma unroll
        for (int i = 0; i < VV; i++) { float e = __expf(row[i] - m); row[i] = e; s += e; }
        float inv = 1.f / s;
        #pragma unroll
        for (int i = 0; i < VV; i++) row[i] *= inv;
    }
    __syncthreads();

    // ---- o = attn @ v  -> xno ----
    for (int k = tid; k < VV * DA; k += THREADS) {
        int vq = k / DA, dd = k - vq * DA, h = dd >> 5;
        const float* arow = sc + (h * VV + vq) * VV;
        float acc = 0.f;
        #pragma unroll
        for (int kv = 0; kv < VV; kv++) acc += arow[kv] * hq[kv * (3 * DA) + 2 * DA + dd];
        xno[k] = acc;
    }
    __syncthreads();

    // ---- out projection -> xcn[:, 384:] ----
    for (int k = tid; k < VV * DA; k += THREADS) {
        int v = k / DA, j = k - v * DA;
        const float* wr = out_w + (size_t)j * DA;
        const float* xr = xno + v * DA;
        float acc = out_b[j];
        #pragma unroll 8
        for (int d = 0; d < DA; d += 4) {
            float4 w4 = *(const float4*)(wr + d);
            float4 x4 = *(const float4*)(xr + d);
            acc += x4.x * w4.x + x4.y * w4.y + x4.z * w4.z + x4.w * w4.w;
        }
        xcn[v * DD + DM + j] = acc;
    }
    __syncthreads();

    // ---- rmsnorm over D=512, in place on xcn, with nf_w ----
    for (int v = warp; v < VV; v += nwarp) {
        float s = 0.f;
        for (int d = lane; d < DD; d += 32) { float t = xcn[v * DD + d]; s += t * t; }
        #pragma unroll
        for (int o = 16; o; o >>= 1) s += __shfl_xor_sync(0xffffffffu, s, o);
        float r = rsqrtf(s * (1.0f / DD) + 1e-6f);
        for (int d = lane; d < DD; d += 32) xcn[v * DD + d] *= r * nf_w[d];
    }
    __syncthreads();

    // ---- channel MLP, chunked over hidden (8 chunks of 128) ----
    // thread owns output column d = tid for all 17 rows
    const int d = tid;                 // THREADS == 512 == DD
    float acc[VV];
    {
        float b2v = cm_b2[d];
        #pragma unroll
        for (int v = 0; v < VV; v++) acc[v] = b2v;
    }
    for (int c = 0; c < 8; c++) {
        const int j0 = c * 128;
        // phase 1: h1c[v][j] = gelu(xcn[v] . cm_w1[j0+j] + b1)
        for (int k = tid; k < VV * 128; k += THREADS) {
            int v = k >> 7, j = k & 127;
            const float* wr = cm_w1 + (size_t)(j0 + j) * DD;
            const float* xr = xcn + v * DD;
            float a = cm_b1[j0 + j];
            #pragma unroll 8
            for (int d2 = 0; d2 < DD; d2 += 4) {
                float4 w4 = *(const float4*)(wr + d2);
                float4 x4 = *(const float4*)(xr + d2);
                a += x4.x * w4.x + x4.y * w4.y + x4.z * w4.z + x4.w * w4.w;
            }
            h1c[k] = gelu_exact(a);
        }
        __syncthreads();
        // phase 2: acc[v] += h1c[v][:] . cm_w2[d][j0:j0+128]
        const float* wr2 = cm_w2 + (size_t)d * 1024 + j0;
        #pragma unroll 4
        for (int j = 0; j < 128; j += 4) {
            float4 w4 = *(const float4*)(wr2 + j);
            #pragma unroll
            for (int v = 0; v < VV; v++) {
                float4 h4 = *(const float4*)(h1c + v * 128 + j);
                acc[v] += h4.x * w4.x + h4.y * w4.y + h4.z * w4.z + h4.w * w4.w;
            }
        }
        __syncthreads();
    }

    // ---- residual epilogue: out = x + y ----
    float* og = out + base;
    #pragma unroll
    for (int v = 0; v < VV; v++) og[v * DD + d] = xs[v * DD + d] + acc[v];
}

extern "C" void kernel_launch(void* const* d_in, const int* in_sizes, int n_in,
                              void* d_out, int out_size)
{
    const float* x     = (const float*)d_in[0];
    const float* tm_w1 = (const float*)d_in[1];
    const float* tm_b1 = (const float*)d_in[2];
    const float* tm_w2 = (const float*)d_in[3];
    const float* tm_b2 = (const float*)d_in[4];
    const float* na_w  = (const float*)d_in[5];
    const float* in_w  = (const float*)d_in[6];
    const float* in_b  = (const float*)d_in[7];
    const float* out_w = (const float*)d_in[8];
    const float* out_b = (const float*)d_in[9];
    const float* nf_w  = (const float*)d_in[10];
    const float* cm_w1 = (const float*)d_in[11];
    const float* cm_b1 = (const float*)d_in[12];
    const float* cm_w2 = (const float*)d_in[13];
    const float* cm_b2 = (const float*)d_in[14];
    float* out = (float*)d_out;

    cudaFuncSetAttribute(spatial_mixer_fused,
                         cudaFuncAttributeMaxDynamicSharedMemorySize, SMEM_BYTES);
    spatial_mixer_fused<<<BT, THREADS, SMEM_BYTES>>>(
        x, tm_w1, tm_b1, tm_w2, tm_b2, na_w, in_w, in_b, out_w, out_b,
        nf_w, cm_w1, cm_b1, cm_w2, cm_b2, out);
}

// round 2
// speedup vs baseline: 2.6227x; 2.6227x over previous
#include <cuda_runtime.h>
#include <math.h>

#define NN 32
#define TT 243
#define VV 17
#define DD 512
#define DM 384
#define DA 128
#define NH 4
#define HD 32
#define BT (NN*TT)            // 7776 blocks
#define ROW_ELEMS (VV*DD)     // 8704 floats per (n,t) slice
#define THREADS 512
#define WLD 513               // padded row stride of transposed weight tile

// ---- shared memory layout (floats) ----
#define OFF_XS   0                        // 17*512 original x (residual)
#define OFF_XCN  (OFF_XS  + 8704)         // 17*512 concat / normalized
#define OFF_HQ   (OFF_XCN + 8704)         // 17*384 tm hidden, then qkv
#define OFF_XNO  (OFF_HQ  + 6528)         // 17*128 rmsnorm(xa), then attn o
#define OFF_SC   (OFF_XNO + 2176)         // 4*17*17 scores
#define OFF_H1C  (OFF_SC  + 1160)         // 17*512 MLP hidden (one 512-pass)
#define OFF_WT   (OFF_H1C + 8704)         // 32*513 transposed weight tile
#define OFF_W1   (OFF_WT  + 32*WLD)       // 289
#define OFF_W2   (OFF_W1  + 289)          // 289
#define OFF_B1   (OFF_W2  + 289)          // 17
#define OFF_B2   (OFF_B1  + 17)           // 17
#define SMEM_FLOATS (OFF_B2 + 17 + 4)
#define SMEM_BYTES (SMEM_FLOATS * 4)

typedef unsigned long long ull;

__device__ __forceinline__ ull pack2(float lo, float hi) {
    ull r; asm("mov.b64 %0, {%1, %2};" : "=l"(r) : "f"(lo), "f"(hi)); return r;
}
__device__ __forceinline__ float2 unpack2(ull v) {
    float2 r; asm("mov.b64 {%0, %1}, %2;" : "=f"(r.x), "=f"(r.y) : "l"(v)); return r;
}
__device__ __forceinline__ void ffma2(ull& acc, ull a, ull b) {
    asm("fma.rn.f32x2 %0, %1, %2, %0;" : "+l"(acc) : "l"(a), "l"(b));
}
__device__ __forceinline__ float gelu_exact(float v) {
    return 0.5f * v * (1.0f + erff(v * 0.7071067811865475f));
}

// Stage a [32 k][nrows j] transposed tile: wt[kk*WLD + j] = gw[j*ldw + koff + kk].
// Global: warp reads one 128B-contiguous row segment (1 wavefront / warp-LDG).
// Smem:   STS stride WLD=513 floats -> banks l*513 mod 32 = l (conflict-free).
__device__ __forceinline__ void stage_wt(float* __restrict__ wt,
                                         const float* __restrict__ gw,
                                         int ldw, int nrows, int koff) {
    const int lane = threadIdx.x & 31, warp = threadIdx.x >> 5;
    const float* g = gw + koff + lane;
    #pragma unroll 1
    for (int j = warp; j < nrows; j += 16)
        wt[lane * WLD + j] = g[(size_t)j * ldw];
}

// One 32-wide k-tile of MAC: thread owns output column j, NV row accumulators.
// Weights: conflict-free LDS.32; activations: broadcast LDS.128 (ulonglong2 =
// two pre-packed f32x2 operands); math: fma.rn.f32x2 (2 FLOPs/lane/inst).
template<int NV>
__device__ __forceinline__ void tile_mac(const float* __restrict__ xin, int xld,
                                         int k0, const float* __restrict__ wt,
                                         int j, ull* acc) {
    #pragma unroll
    for (int kk = 0; kk < 32; kk += 4) {
        ull w01 = pack2(wt[(kk+0)*WLD + j], wt[(kk+1)*WLD + j]);
        ull w23 = pack2(wt[(kk+2)*WLD + j], wt[(kk+3)*WLD + j]);
        const float* xp = xin + k0 + kk;
        #pragma unroll
        for (int v = 0; v < NV; v++) {
            ulonglong2 x = *(const ulonglong2*)(xp + v * xld);
            ffma2(acc[v], x.x, w01);
            ffma2(acc[v], x.y, w23);
        }
    }
}

__device__ __forceinline__ void tile_mac_range(const float* __restrict__ xin, int xld,
                                               int k0, const float* __restrict__ wt,
                                               int j, ull* acc, int v0, int v1) {
    #pragma unroll
    for (int kk = 0; kk < 32; kk += 4) {
        ull w01 = pack2(wt[(kk+0)*WLD + j], wt[(kk+1)*WLD + j]);
        ull w23 = pack2(wt[(kk+2)*WLD + j], wt[(kk+3)*WLD + j]);
        const float* xp = xin + k0 + kk;
        #pragma unroll 5
        for (int v = v0; v < v1; v++) {
            ulonglong2 x = *(const ulonglong2*)(xp + v * xld);
            ffma2(acc[v - v0], x.x, w01);
            ffma2(acc[v - v0], x.y, w23);
        }
    }
}

extern "C" __global__ void __launch_bounds__(THREADS, 1)
spatial_mixer_fused(const float* __restrict__ x,
                    const float* __restrict__ tm_w1, const float* __restrict__ tm_b1,
                    const float* __restrict__ tm_w2, const float* __restrict__ tm_b2,
                    const float* __restrict__ na_w,
                    const float* __restrict__ in_w,  const float* __restrict__ in_b,
                    const float* __restrict__ out_w, const float* __restrict__ out_b,
                    const float* __restrict__ nf_w,
                    const float* __restrict__ cm_w1, const float* __restrict__ cm_b1,
                    const float* __restrict__ cm_w2, const float* __restrict__ cm_b2,
                    float* __restrict__ out)
{
    extern __shared__ float sm[];
    float* xs  = sm + OFF_XS;
    float* xcn = sm + OFF_XCN;
    float* hq  = sm + OFF_HQ;
    float* xno = sm + OFF_XNO;
    float* sc  = sm + OFF_SC;
    float* h1c = sm + OFF_H1C;
    float* wt  = sm + OFF_WT;
    float* w1s = sm + OFF_W1;
    float* w2s = sm + OFF_W2;
    float* b1s = sm + OFF_B1;
    float* b2s = sm + OFF_B2;

    const int tid  = threadIdx.x;
    const int warp = tid >> 5;
    const int lane = tid & 31;
    const size_t base = (size_t)blockIdx.x * ROW_ELEMS;
    const float* xg = x + base;

    // ---- load x slice + token-mixer weights ----
    for (int i = tid; i < ROW_ELEMS; i += THREADS) xs[i] = xg[i];
    for (int i = tid; i < 289; i += THREADS) { w1s[i] = tm_w1[i]; w2s[i] = tm_w2[i]; }
    if (tid < 17) { b1s[tid] = tm_b1[tid]; b2s[tid] = tm_b2[tid]; }
    __syncthreads();

    // ---- token mixer stage 1: h = gelu(w1 @ xm + b1) ----
    for (int k = tid; k < VV * DM; k += THREADS) {
        int u = k / DM, d = k - u * DM;
        float acc = b1s[u];
        #pragma unroll
        for (int v = 0; v < VV; v++) acc += w1s[u * 17 + v] * xs[v * DD + d];
        hq[u * DM + d] = gelu_exact(acc);
    }
    __syncthreads();

    // ---- token mixer stage 2 -> xcn[:, :384];  rmsnorm(xa) -> xno ----
    for (int k = tid; k < VV * DM; k += THREADS) {
        int u = k / DM, d = k - u * DM;
        float acc = b2s[u];
        #pragma unroll
        for (int v = 0; v < VV; v++) acc += w2s[u * 17 + v] * hq[v * DM + d];
        xcn[u * DD + d] = acc;
    }
    for (int v = warp; v < VV; v += 16) {
        float s = 0.f;
        for (int d = lane; d < DA; d += 32) { float t = xs[v * DD + DM + d]; s += t * t; }
        #pragma unroll
        for (int o = 16; o; o >>= 1) s += __shfl_xor_sync(0xffffffffu, s, o);
        float r = rsqrtf(s * (1.0f / DA) + 1e-6f);
        for (int d = lane; d < DA; d += 32)
            xno[v * DA + d] = xs[v * DD + DM + d] * r * na_w[d];
    }
    __syncthreads();

    // ---- qkv = xn @ in_w.T + in_b  (staged tiles, 4 k-tiles of 32) ----
    {
        ull accQ[VV];
        #pragma unroll
        for (int v = 0; v < VV; v++) accQ[v] = 0ull;
        #pragma unroll 1
        for (int kt = 0; kt < 4; kt++) {
            __syncthreads();
            stage_wt(wt, in_w, DA, 3 * DA, kt * 32);
            __syncthreads();
            if (tid < 3 * DA) tile_mac<VV>(xno, DA, kt * 32, wt, tid, accQ);
        }
        if (tid < 3 * DA) {
            float b = in_b[tid];
            #pragma unroll
            for (int v = 0; v < VV; v++) {
                float2 s = unpack2(accQ[v]);
                hq[v * 384 + tid] = s.x + s.y + b;
            }
        }
    }
    __syncthreads();

    // ---- attention scores ----
    for (int k = tid; k < NH * VV * VV; k += THREADS) {
        int h = k / (VV * VV), r = k - h * VV * VV, qv = r / VV, kv = r - qv * VV;
        const float* qp = hq + qv * 384 + h * HD;
        const float* kp = hq + kv * 384 + DA + h * HD;
        float s = 0.f;
        #pragma unroll
        for (int d = 0; d < HD; d++) s += qp[d] * kp[d];
        sc[k] = s * 0.17677669529663687f;
    }
    __syncthreads();

    // ---- softmax (68 rows of 17) ----
    for (int r = tid; r < NH * VV; r += THREADS) {
        float* row = sc + r * VV;
        float m = row[0];
        #pragma unroll
        for (int i = 1; i < VV; i++) m = fmaxf(m, row[i]);
        float s = 0.f;
        #pragma unroll
        for (int i = 0; i < VV; i++) { float e = __expf(row[i] - m); row[i] = e; s += e; }
        float inv = 1.f / s;
        #pragma unroll
        for (int i = 0; i < VV; i++) row[i] *= inv;
    }
    __syncthreads();

    // ---- o = attn @ v  -> xno ----
    for (int k = tid; k < VV * DA; k += THREADS) {
        int vq = k / DA, dd = k - vq * DA, h = dd >> 5;
        const float* arow = sc + (h * VV + vq) * VV;
        float acc = 0.f;
        #pragma unroll
        for (int kv = 0; kv < VV; kv++) acc += arow[kv] * hq[kv * 384 + 2 * DA + dd];
        xno[k] = acc;
    }

    // ---- out projection -> xcn[:, 384:]  (staged, v split over 4 groups) ----
    {
        const int g  = tid >> 7, j = tid & 127;
        const int v0 = (17 * g) >> 2, v1 = (17 * (g + 1)) >> 2;   // 4,4,4,5 rows
        ull accO[5];
        #pragma unroll
        for (int i = 0; i < 5; i++) accO[i] = 0ull;
        #pragma unroll 1
        for (int kt = 0; kt < 4; kt++) {
            __syncthreads();
            stage_wt(wt, out_w, DA, DA, kt * 32);
            __syncthreads();
            tile_mac_range(xno, DA, kt * 32, wt, j, accO, v0, v1);
        }
        float b = out_b[j];
        __syncthreads();                       // xno fully consumed by all groups
        for (int v = v0; v < v1; v++) {
            float2 s = unpack2(accO[v - v0]);
            xcn[v * DD + DM + j] = s.x + s.y + b;
        }
    }
    __syncthreads();

    // ---- rmsnorm over D=512 in place on xcn ----
    for (int v = warp; v < VV; v += 16) {
        float s = 0.f;
        for (int d = lane; d < DD; d += 32) { float t = xcn[v * DD + d]; s += t * t; }
        #pragma unroll
        for (int o = 16; o; o >>= 1) s += __shfl_xor_sync(0xffffffffu, s, o);
        float r = rsqrtf(s * (1.0f / DD) + 1e-6f);
        for (int d = lane; d < DD; d += 32) xcn[v * DD + d] *= r * nf_w[d];
    }

    // ---- channel MLP: 2 passes of 512 hidden, staged weight tiles ----
    ull accB[VV];
    #pragma unroll
    for (int v = 0; v < VV; v++) accB[v] = 0ull;

    #pragma unroll 1
    for (int p = 0; p < 2; p++) {
        // phase A: hidden column j = p*512 + tid
        ull accA[VV];
        #pragma unroll
        for (int v = 0; v < VV; v++) accA[v] = 0ull;
        const float* gw1 = cm_w1 + (size_t)(p * 512) * DD;
        #pragma unroll 1
        for (int kt = 0; kt < 16; kt++) {
            __syncthreads();
            stage_wt(wt, gw1, DD, 512, kt * 32);
            __syncthreads();
            tile_mac<VV>(xcn, DD, kt * 32, wt, tid, accA);
        }
        float b1 = cm_b1[p * 512 + tid];
        #pragma unroll
        for (int v = 0; v < VV; v++) {
            float2 s = unpack2(accA[v]);
            h1c[v * 512 + tid] = gelu_exact(s.x + s.y + b1);
        }
        // phase B: accumulate this pass's 512 k into accB (dout = tid)
        const float* gw2 = cm_w2 + p * 512;
        #pragma unroll 1
        for (int kt = 0; kt < 16; kt++) {
            __syncthreads();                 // also orders h1c writes
            stage_wt(wt, gw2, 2 * DD, 512, kt * 32);
            __syncthreads();
            tile_mac<VV>(h1c, 512, kt * 32, wt, tid, accB);
        }
    }

    // ---- residual epilogue ----
    {
        float b2 = cm_b2[tid];
        float* og = out + base;
        #pragma unroll
        for (int v = 0; v < VV; v++) {
            float2 s = unpack2(accB[v]);
            og[v * DD + tid] = xs[v * DD + tid] + s.x + s.y + b2;
        }
    }
}

extern "C" void kernel_launch(void* const* d_in, const int* in_sizes, int n_in,
                              void* d_out, int out_size)
{
    const float* x     = (const float*)d_in[0];
    const float* tm_w1 = (const float*)d_in[1];
    const float* tm_b1 = (const float*)d_in[2];
    const float* tm_w2 = (const float*)d_in[3];
    const float* tm_b2 = (const float*)d_in[4];
    const float* na_w  = (const float*)d_in[5];
    const float* in_w  = (const float*)d_in[6];
    const float* in_b  = (const float*)d_in[7];
    const float* out_w = (const float*)d_in[8];
    const float* out_b = (const float*)d_in[9];
    const float* nf_w  = (const float*)d_in[10];
    const float* cm_w1 = (const float*)d_in[11];
    const float* cm_b1 = (const float*)d_in[12];
    const float* cm_w2 = (const float*)d_in[13];
    const float* cm_b2 = (const float*)d_in[14];
    float* out = (float*)d_out;

    cudaFuncSetAttribute(spatial_mixer_fused,
                         cudaFuncAttributeMaxDynamicSharedMemorySize, SMEM_BYTES);
    spatial_mixer_fused<<<BT, THREADS, SMEM_BYTES>>>(
        x, tm_w1, tm_b1, tm_w2, tm_b2, na_w, in_w, in_b, out_w, out_b,
        nf_w, cm_w1, cm_b1, cm_w2, cm_b2, out);
}

// round 3
// speedup vs baseline: 4.1170x; 1.5698x over previous
#include <cuda_runtime.h>
#include <math.h>

#define NN 32
#define TT 243
#define VV 17
#define DD 512
#define DM 384
#define DA 128
#define NH 4
#define HD 32
#define BT (NN*TT)
#define ROW_ELEMS (VV*DD)
#define THREADS 512
#define WLD 513               // padded row stride of transposed weight tile
#define KT 16                 // k per staged tile

// ---- shared memory layout (floats) ----
#define OFF_XS   0                        // 17*512 original x (residual)
#define OFF_XCN  (OFF_XS  + 8704)         // 17*512 concat / normalized
#define OFF_HQ   (OFF_XCN + 8704)         // 17*384 tm hidden, then qkv
#define OFF_XNO  (OFF_HQ  + 6528)         // 17*128 rmsnorm(xa), then attn o
#define OFF_SC   (OFF_XNO + 2176)         // 4*17*17 scores
#define OFF_H1C  (OFF_SC  + 1160)         // 17*512 MLP hidden (one 512-pass)
#define OFF_WT   (OFF_H1C + 8704)         // 2 buffers of 16*513
#define OFF_W1   (OFF_WT  + 2*KT*WLD)     // 289
#define OFF_W2   (OFF_W1  + 289)          // 289
#define OFF_B1   (OFF_W2  + 289)          // 17
#define OFF_B2   (OFF_B1  + 17)           // 17
#define SMEM_FLOATS (OFF_B2 + 17 + 4)
#define SMEM_BYTES (SMEM_FLOATS * 4)

typedef unsigned long long ull;

__device__ __forceinline__ ull pack2(float lo, float hi) {
    ull r; asm("mov.b64 %0, {%1, %2};" : "=l"(r) : "f"(lo), "f"(hi)); return r;
}
__device__ __forceinline__ float2 unpack2(ull v) {
    float2 r; asm("mov.b64 {%0, %1}, %2;" : "=f"(r.x), "=f"(r.y) : "l"(v)); return r;
}
__device__ __forceinline__ void ffma2(ull& acc, ull a, ull b) {
    asm("fma.rn.f32x2 %0, %1, %2, %0;" : "+l"(acc) : "l"(a), "l"(b));
}
__device__ __forceinline__ float gelu_exact(float v) {
    return 0.5f * v * (1.0f + erff(v * 0.7071067811865475f));
}
__device__ __forceinline__ void cp_commit() {
    asm volatile("cp.async.commit_group;" ::: "memory");
}
__device__ __forceinline__ void cp_wait0() {
    asm volatile("cp.async.wait_group 0;" ::: "memory");
}
__device__ __forceinline__ void cp_wait1() {
    asm volatile("cp.async.wait_group 1;" ::: "memory");
}

// Stage one [KT k][nrows j] transposed tile via cp.async (pipelined, no regs).
// Half-warp reads 16 consecutive floats of a weight row (64B coalesced);
// STS pattern is <=2-way conflicted (absorbed by cp.async hardware path).
__device__ __forceinline__ void stage16(float* __restrict__ wtb,
                                        const float* __restrict__ gw,
                                        int ldw, int nrows, int koff) {
    const int lane = threadIdx.x & 31, warp = threadIdx.x >> 5;
    const int kk = lane & 15;
    const int jh = lane >> 4;
    unsigned dstb = (unsigned)__cvta_generic_to_shared(wtb);
    const float* g = gw + koff + kk;
    #pragma unroll 1
    for (int j = warp * 2 + jh; j < nrows; j += 32) {
        unsigned dst = dstb + (unsigned)(kk * WLD + j) * 4u;
        const float* src = g + (size_t)j * ldw;
        asm volatile("cp.async.ca.shared.global [%0], [%1], 4;" :: "r"(dst), "l"(src));
    }
    cp_commit();
}

// One KT-wide k-tile MAC: thread owns output column j, NV row accumulators.
template<int NV>
__device__ __forceinline__ void tile_mac16(const float* __restrict__ xin, int xld,
                                           int k0, const float* __restrict__ wtb,
                                           int j, ull* acc) {
    #pragma unroll
    for (int kk = 0; kk < KT; kk += 4) {
        ull w01 = pack2(wtb[(kk+0)*WLD + j], wtb[(kk+1)*WLD + j]);
        ull w23 = pack2(wtb[(kk+2)*WLD + j], wtb[(kk+3)*WLD + j]);
        const float* xp = xin + k0 + kk;
        #pragma unroll
        for (int v = 0; v < NV; v++) {
            ulonglong2 x = *(const ulonglong2*)(xp + v * xld);
            ffma2(acc[v], x.x, w01);
            ffma2(acc[v], x.y, w23);
        }
    }
}

extern "C" __global__ void __launch_bounds__(THREADS, 1)
spatial_mixer_fused(const float* __restrict__ x,
                    const float* __restrict__ tm_w1, const float* __restrict__ tm_b1,
                    const float* __restrict__ tm_w2, const float* __restrict__ tm_b2,
                    const float* __restrict__ na_w,
                    const float* __restrict__ in_w,  const float* __restrict__ in_b,
                    const float* __restrict__ out_w, const float* __restrict__ out_b,
                    const float* __restrict__ nf_w,
                    const float* __restrict__ cm_w1, const float* __restrict__ cm_b1,
                    const float* __restrict__ cm_w2, const float* __restrict__ cm_b2,
                    float* __restrict__ out)
{
    extern __shared__ float sm[];
    float* xs  = sm + OFF_XS;
    float* xcn = sm + OFF_XCN;
    float* hq  = sm + OFF_HQ;
    float* xno = sm + OFF_XNO;
    float* sc  = sm + OFF_SC;
    float* h1c = sm + OFF_H1C;
    float* wtA = sm + OFF_WT;
    float* wtB = sm + OFF_WT + KT * WLD;
    float* w1s = sm + OFF_W1;
    float* w2s = sm + OFF_W2;
    float* b1s = sm + OFF_B1;
    float* b2s = sm + OFF_B2;

    const int tid  = threadIdx.x;
    const int warp = tid >> 5;
    const int lane = tid & 31;
    const size_t base = (size_t)blockIdx.x * ROW_ELEMS;
    const float* xg = x + base;

    // ---- load x slice + token-mixer weights ----
    for (int i = tid; i < ROW_ELEMS; i += THREADS) xs[i] = xg[i];
    for (int i = tid; i < 289; i += THREADS) { w1s[i] = tm_w1[i]; w2s[i] = tm_w2[i]; }
    if (tid < 17) { b1s[tid] = tm_b1[tid]; b2s[tid] = tm_b2[tid]; }
    __syncthreads();

    // ---- token mixer stage 1: h = gelu(w1 @ xm + b1) ----
    for (int k = tid; k < VV * DM; k += THREADS) {
        int u = k / DM, d = k - u * DM;
        float acc = b1s[u];
        #pragma unroll
        for (int v = 0; v < VV; v++) acc += w1s[u * 17 + v] * xs[v * DD + d];
        hq[u * DM + d] = gelu_exact(acc);
    }
    __syncthreads();

    // ---- token mixer stage 2 -> xcn[:, :384];  rmsnorm(xa) -> xno ----
    for (int k = tid; k < VV * DM; k += THREADS) {
        int u = k / DM, d = k - u * DM;
        float acc = b2s[u];
        #pragma unroll
        for (int v = 0; v < VV; v++) acc += w2s[u * 17 + v] * hq[v * DM + d];
        xcn[u * DD + d] = acc;
    }
    for (int v = warp; v < VV; v += 16) {
        float s = 0.f;
        for (int d = lane; d < DA; d += 32) { float t = xs[v * DD + DM + d]; s += t * t; }
        #pragma unroll
        for (int o = 16; o; o >>= 1) s += __shfl_xor_sync(0xffffffffu, s, o);
        float r = rsqrtf(s * (1.0f / DA) + 1e-6f);
        for (int d = lane; d < DA; d += 32)
            xno[v * DA + d] = xs[v * DD + DM + d] * r * na_w[d];
    }
    __syncthreads();

    // ---- qkv = xn @ in_w.T + in_b  (pipelined, 8 tiles of 16 k) ----
    {
        ull accQ[VV];
        #pragma unroll
        for (int v = 0; v < VV; v++) accQ[v] = 0ull;
        stage16(wtA, in_w, DA, 3 * DA, 0);
        #pragma unroll 1
        for (int t = 0; t < 8; t++) {
            if (t + 1 < 8) stage16((t & 1) ? wtA : wtB, in_w, DA, 3 * DA, (t + 1) * KT);
            if (t + 1 < 8) cp_wait1(); else cp_wait0();
            __syncthreads();
            if (tid < 3 * DA)
                tile_mac16<VV>(xno, DA, t * KT, (t & 1) ? wtB : wtA, tid, accQ);
            __syncthreads();
        }
        if (tid < 3 * DA) {
            float b = in_b[tid];
            #pragma unroll
            for (int v = 0; v < VV; v++) {
                float2 s = unpack2(accQ[v]);
                hq[v * 384 + tid] = s.x + s.y + b;
            }
        }
    }
    __syncthreads();

    // ---- attention scores ----
    for (int k = tid; k < NH * VV * VV; k += THREADS) {
        int h = k / (VV * VV), r = k - h * VV * VV, qv = r / VV, kv = r - qv * VV;
        const float* qp = hq + qv * 384 + h * HD;
        const float* kp = hq + kv * 384 + DA + h * HD;
        float s = 0.f;
        #pragma unroll
        for (int d = 0; d < HD; d++) s += qp[d] * kp[d];
        sc[k] = s * 0.17677669529663687f;
    }
    __syncthreads();

    // ---- softmax (68 rows of 17) ----
    for (int r = tid; r < NH * VV; r += THREADS) {
        float* row = sc + r * VV;
        float m = row[0];
        #pragma unroll
        for (int i = 1; i < VV; i++) m = fmaxf(m, row[i]);
        float s = 0.f;
        #pragma unroll
        for (int i = 0; i < VV; i++) { float e = __expf(row[i] - m); row[i] = e; s += e; }
        float inv = 1.f / s;
        #pragma unroll
        for (int i = 0; i < VV; i++) row[i] *= inv;
    }
    __syncthreads();

    // ---- o = attn @ v  -> xno ----
    for (int k = tid; k < VV * DA; k += THREADS) {
        int vq = k / DA, dd = k - vq * DA, h = dd >> 5;
        const float* arow = sc + (h * VV + vq) * VV;
        float acc = 0.f;
        #pragma unroll
        for (int kv = 0; kv < VV; kv++) acc += arow[kv] * hq[kv * 384 + 2 * DA + dd];
        xno[k] = acc;
    }
    __syncthreads();

    // ---- out projection -> xcn[:, 384:]  (pipelined, 8 tiles) ----
    {
        ull accO[VV];
        #pragma unroll
        for (int v = 0; v < VV; v++) accO[v] = 0ull;
        stage16(wtA, out_w, DA, DA, 0);
        #pragma unroll 1
        for (int t = 0; t < 8; t++) {
            if (t + 1 < 8) stage16((t & 1) ? wtA : wtB, out_w, DA, DA, (t + 1) * KT);
            if (t + 1 < 8) cp_wait1(); else cp_wait0();
            __syncthreads();
            if (tid < DA)
                tile_mac16<VV>(xno, DA, t * KT, (t & 1) ? wtB : wtA, tid, accO);
            __syncthreads();
        }
        if (tid < DA) {
            float b = out_b[tid];
            #pragma unroll
            for (int v = 0; v < VV; v++) {
                float2 s = unpack2(accO[v]);
                xcn[v * DD + DM + tid] = s.x + s.y + b;
            }
        }
    }
    __syncthreads();

    // ---- rmsnorm over D=512 in place on xcn ----
    for (int v = warp; v < VV; v += 16) {
        float s = 0.f;
        for (int d = lane; d < DD; d += 32) { float t = xcn[v * DD + d]; s += t * t; }
        #pragma unroll
        for (int o = 16; o; o >>= 1) s += __shfl_xor_sync(0xffffffffu, s, o);
        float r = rsqrtf(s * (1.0f / DD) + 1e-6f);
        for (int d = lane; d < DD; d += 32) xcn[v * DD + d] *= r * nf_w[d];
    }
    __syncthreads();

    // ---- channel MLP: 2 passes of 512 hidden, pipelined 16-k weight tiles ----
    ull accB[VV];
    #pragma unroll
    for (int v = 0; v < VV; v++) accB[v] = 0ull;

    #pragma unroll 1
    for (int p = 0; p < 2; p++) {
        // phase A: hidden column j = p*512 + tid,  K=512 -> 32 tiles
        ull accA[VV];
        #pragma unroll
        for (int v = 0; v < VV; v++) accA[v] = 0ull;
        const float* gw1 = cm_w1 + (size_t)(p * 512) * DD;
        stage16(wtA, gw1, DD, 512, 0);
        #pragma unroll 1
        for (int t = 0; t < 32; t++) {
            if (t + 1 < 32) stage16((t & 1) ? wtA : wtB, gw1, DD, 512, (t + 1) * KT);
            if (t + 1 < 32) cp_wait1(); else cp_wait0();
            __syncthreads();
            tile_mac16<VV>(xcn, DD, t * KT, (t & 1) ? wtB : wtA, tid, accA);
            __syncthreads();
        }
        float b1 = cm_b1[p * 512 + tid];
        #pragma unroll
        for (int v = 0; v < VV; v++) {
            float2 s = unpack2(accA[v]);
            h1c[v * 512 + tid] = gelu_exact(s.x + s.y + b1);
        }
        // phase B: accumulate this pass's 512 k into accB (dout = tid)
        const float* gw2 = cm_w2 + p * 512;
        stage16(wtA, gw2, 2 * DD, 512, 0);
        #pragma unroll 1
        for (int t = 0; t < 32; t++) {
            if (t + 1 < 32) stage16((t & 1) ? wtA : wtB, gw2, 2 * DD, 512, (t + 1) * KT);
            if (t + 1 < 32) cp_wait1(); else cp_wait0();
            __syncthreads();      // also orders h1c writes on first iteration
            tile_mac16<VV>(h1c, 512, t * KT, (t & 1) ? wtB : wtA, tid, accB);
            __syncthreads();
        }
    }

    // ---- residual epilogue ----
    {
        float b2 = cm_b2[tid];
        float* og = out + base;
        #pragma unroll
        for (int v = 0; v < VV; v++) {
            float2 s = unpack2(accB[v]);
            og[v * DD + tid] = xs[v * DD + tid] + s.x + s.y + b2;
        }
    }
}

extern "C" void kernel_launch(void* const* d_in, const int* in_sizes, int n_in,
                              void* d_out, int out_size)
{
    const float* x     = (const float*)d_in[0];
    const float* tm_w1 = (const float*)d_in[1];
    const float* tm_b1 = (const float*)d_in[2];
    const float* tm_w2 = (const float*)d_in[3];
    const float* tm_b2 = (const float*)d_in[4];
    const float* na_w  = (const float*)d_in[5];
    const float* in_w  = (const float*)d_in[6];
    const float* in_b  = (const float*)d_in[7];
    const float* out_w = (const float*)d_in[8];
    const float* out_b = (const float*)d_in[9];
    const float* nf_w  = (const float*)d_in[10];
    const float* cm_w1 = (const float*)d_in[11];
    const float* cm_b1 = (const float*)d_in[12];
    const float* cm_w2 = (const float*)d_in[13];
    const float* cm_b2 = (const float*)d_in[14];
    float* out = (float*)d_out;

    cudaFuncSetAttribute(spatial_mixer_fused,
                         cudaFuncAttributeMaxDynamicSharedMemorySize, SMEM_BYTES);
    spatial_mixer_fused<<<BT, THREADS, SMEM_BYTES>>>(
        x, tm_w1, tm_b1, tm_w2, tm_b2, na_w, in_w, in_b, out_w, out_b,
        nf_w, cm_w1, cm_b1, cm_w2, cm_b2, out);
}

// round 4
// speedup vs baseline: 5.0854x; 1.2352x over previous
#include <cuda_runtime.h>
#include <math.h>

#define NN 32
#define TT 243
#define VV 17
#define DD 512
#define DM 384
#define DA 128
#define NH 4
#define HD 32
#define BT (NN*TT)
#define ROW_ELEMS (VV*DD)
#define THREADS 512
#define WR 20                 // row stride (floats) of staged weight tile: 80B,
                              // 16B-aligned rows, conflict-free LDS.128 (20l mod 32
                              // over 8-lane phase = perfect bank partition)
#define KT 16                 // k per staged tile

// ---- shared memory layout (floats) ----
#define OFF_XS   0                        // 17*512 original x (residual)
#define OFF_XCN  (OFF_XS  + 8704)         // 17*512 concat / normalized
#define OFF_HQ   (OFF_XCN + 8704)         // 17*384 tm hidden, then qkv
#define OFF_XNO  (OFF_HQ  + 6528)         // 17*128 rmsnorm(xa), then attn o
#define OFF_SC   (OFF_XNO + 2176)         // 4*17*17 scores
#define OFF_H1C  OFF_HQ                   // 17*512 MLP hidden, aliases dead hq+xno
#define OFF_WT   (OFF_SC  + 1160)         // 2 buffers of 512*WR
#define OFF_W1   (OFF_WT  + 2*512*WR)     // 289
#define OFF_W2   (OFF_W1  + 289)          // 289
#define OFF_B1   (OFF_W2  + 289)          // 17
#define OFF_B2   (OFF_B1  + 17)           // 17
#define SMEM_FLOATS (OFF_B2 + 17 + 4)
#define SMEM_BYTES (SMEM_FLOATS * 4)

typedef unsigned long long ull;

__device__ __forceinline__ ull pack2(float lo, float hi) {
    ull r; asm("mov.b64 %0, {%1, %2};" : "=l"(r) : "f"(lo), "f"(hi)); return r;
}
__device__ __forceinline__ float2 unpack2(ull v) {
    float2 r; asm("mov.b64 {%0, %1}, %2;" : "=f"(r.x), "=f"(r.y) : "l"(v)); return r;
}
__device__ __forceinline__ void ffma2(ull& acc, ull a, ull b) {
    asm("fma.rn.f32x2 %0, %1, %2, %0;" : "+l"(acc) : "l"(a), "l"(b));
}
__device__ __forceinline__ float gelu_exact(float v) {
    return 0.5f * v * (1.0f + erff(v * 0.7071067811865475f));
}
__device__ __forceinline__ void cp_commit() {
    asm volatile("cp.async.commit_group;" ::: "memory");
}
__device__ __forceinline__ void cp_wait0() {
    asm volatile("cp.async.wait_group 0;" ::: "memory");
}
__device__ __forceinline__ void cp_wait1() {
    asm volatile("cp.async.wait_group 1;" ::: "memory");
}

// Stage one [nrows j][KT k] row-major tile via 16B cp.async.
// Thread i handles (j = i>>2, chunk c = i&3): 16B from row j, 16B-aligned
// in both gmem (ldw, koff multiples of 4/16) and smem (WR=20 -> 80B rows).
__device__ __forceinline__ void stage16(float* __restrict__ wtb,
                                        const float* __restrict__ gw,
                                        int ldw, int nrows, int koff) {
    unsigned dstb = (unsigned)__cvta_generic_to_shared(wtb);
    const float* g = gw + koff;
    const int n4 = nrows * 4;
    #pragma unroll 1
    for (int i = threadIdx.x; i < n4; i += THREADS) {
        int j = i >> 2, c = i & 3;
        unsigned dst = dstb + (unsigned)(j * WR + c * 4) * 4u;
        const float* src = g + (size_t)j * ldw + c * 4;
        asm volatile("cp.async.cg.shared.global [%0], [%1], 16;" :: "r"(dst), "l"(src));
    }
    cp_commit();
}

// One KT-wide k-tile MAC: thread owns output column j (its own weight row),
// NV row accumulators. Weights: conflict-free LDS.128 of own row; activations:
// broadcast LDS.128 (two pre-packed f32x2); math: fma.rn.f32x2.
template<int NV>
__device__ __forceinline__ void tile_mac16(const float* __restrict__ xin, int xld,
                                           int k0, const float* __restrict__ wtb,
                                           int j, ull* acc) {
    const float4* wr = (const float4*)(wtb + j * WR);
    #pragma unroll
    for (int q = 0; q < 4; q++) {
        float4 w = wr[q];
        ull w01 = pack2(w.x, w.y);
        ull w23 = pack2(w.z, w.w);
        const float* xp = xin + k0 + q * 4;
        #pragma unroll
        for (int v = 0; v < NV; v++) {
            ulonglong2 xv = *(const ulonglong2*)(xp + v * xld);
            ffma2(acc[v], xv.x, w01);
            ffma2(acc[v], xv.y, w23);
        }
    }
}

extern "C" __global__ void __launch_bounds__(THREADS, 1)
spatial_mixer_fused(const float* __restrict__ x,
                    const float* __restrict__ tm_w1, const float* __restrict__ tm_b1,
                    const float* __restrict__ tm_w2, const float* __restrict__ tm_b2,
                    const float* __restrict__ na_w,
                    const float* __restrict__ in_w,  const float* __restrict__ in_b,
                    const float* __restrict__ out_w, const float* __restrict__ out_b,
                    const float* __restrict__ nf_w,
                    const float* __restrict__ cm_w1, const float* __restrict__ cm_b1,
                    const float* __restrict__ cm_w2, const float* __restrict__ cm_b2,
                    float* __restrict__ out)
{
    extern __shared__ float sm[];
    float* xs  = sm + OFF_XS;
    float* xcn = sm + OFF_XCN;
    float* hq  = sm + OFF_HQ;
    float* xno = sm + OFF_XNO;
    float* sc  = sm + OFF_SC;
    float* h1c = sm + OFF_H1C;
    float* wtA = sm + OFF_WT;
    float* wtB = sm + OFF_WT + 512 * WR;
    float* w1s = sm + OFF_W1;
    float* w2s = sm + OFF_W2;
    float* b1s = sm + OFF_B1;
    float* b2s = sm + OFF_B2;

    const int tid  = threadIdx.x;
    const int warp = tid >> 5;
    const int lane = tid & 31;
    const size_t base = (size_t)blockIdx.x * ROW_ELEMS;
    const float* xg = x + base;

    // ---- load x slice + token-mixer weights ----
    for (int i = tid; i < ROW_ELEMS; i += THREADS) xs[i] = xg[i];
    for (int i = tid; i < 289; i += THREADS) { w1s[i] = tm_w1[i]; w2s[i] = tm_w2[i]; }
    if (tid < 17) { b1s[tid] = tm_b1[tid]; b2s[tid] = tm_b2[tid]; }
    __syncthreads();

    // ---- token mixer stage 1: h = gelu(w1 @ xm + b1) ----
    for (int k = tid; k < VV * DM; k += THREADS) {
        int u = k / DM, d = k - u * DM;
        float acc = b1s[u];
        #pragma unroll
        for (int v = 0; v < VV; v++) acc += w1s[u * 17 + v] * xs[v * DD + d];
        hq[u * DM + d] = gelu_exact(acc);
    }
    __syncthreads();

    // ---- token mixer stage 2 -> xcn[:, :384];  rmsnorm(xa) -> xno ----
    for (int k = tid; k < VV * DM; k += THREADS) {
        int u = k / DM, d = k - u * DM;
        float acc = b2s[u];
        #pragma unroll
        for (int v = 0; v < VV; v++) acc += w2s[u * 17 + v] * hq[v * DM + d];
        xcn[u * DD + d] = acc;
    }
    for (int v = warp; v < VV; v += 16) {
        float s = 0.f;
        for (int d = lane; d < DA; d += 32) { float t = xs[v * DD + DM + d]; s += t * t; }
        #pragma unroll
        for (int o = 16; o; o >>= 1) s += __shfl_xor_sync(0xffffffffu, s, o);
        float r = rsqrtf(s * (1.0f / DA) + 1e-6f);
        for (int d = lane; d < DA; d += 32)
            xno[v * DA + d] = xs[v * DD + DM + d] * r * na_w[d];
    }
    __syncthreads();

    // ---- qkv = xn @ in_w.T + in_b  (pipelined, 8 tiles of 16 k) ----
    {
        ull accQ[VV];
        #pragma unroll
        for (int v = 0; v < VV; v++) accQ[v] = 0ull;
        stage16(wtA, in_w, DA, 3 * DA, 0);
        #pragma unroll 1
        for (int t = 0; t < 8; t++) {
            if (t + 1 < 8) stage16((t & 1) ? wtA : wtB, in_w, DA, 3 * DA, (t + 1) * KT);
            if (t + 1 < 8) cp_wait1(); else cp_wait0();
            __syncthreads();
            if (tid < 3 * DA)
                tile_mac16<VV>(xno, DA, t * KT, (t & 1) ? wtB : wtA, tid, accQ);
            __syncthreads();
        }
        if (tid < 3 * DA) {
            float b = in_b[tid];
            #pragma unroll
            for (int v = 0; v < VV; v++) {
                float2 s = unpack2(accQ[v]);
                hq[v * 384 + tid] = s.x + s.y + b;
            }
        }
    }
    __syncthreads();

    // ---- attention scores ----
    for (int k = tid; k < NH * VV * VV; k += THREADS) {
        int h = k / (VV * VV), r = k - h * VV * VV, qv = r / VV, kv = r - qv * VV;
        const float* qp = hq + qv * 384 + h * HD;
        const float* kp = hq + kv * 384 + DA + h * HD;
        float s = 0.f;
        #pragma unroll
        for (int d = 0; d < HD; d++) s += qp[d] * kp[d];
        sc[k] = s * 0.17677669529663687f;
    }
    __syncthreads();

    // ---- softmax (68 rows of 17) ----
    for (int r = tid; r < NH * VV; r += THREADS) {
        float* row = sc + r * VV;
        float m = row[0];
        #pragma unroll
        for (int i = 1; i < VV; i++) m = fmaxf(m, row[i]);
        float s = 0.f;
        #pragma unroll
        for (int i = 0; i < VV; i++) { float e = __expf(row[i] - m); row[i] = e; s += e; }
        float inv = 1.f / s;
        #pragma unroll
        for (int i = 0; i < VV; i++) row[i] *= inv;
    }
    __syncthreads();

    // ---- o = attn @ v  -> xno ----
    for (int k = tid; k < VV * DA; k += THREADS) {
        int vq = k / DA, dd = k - vq * DA, h = dd >> 5;
        const float* arow = sc + (h * VV + vq) * VV;
        float acc = 0.f;
        #pragma unroll
        for (int kv = 0; kv < VV; kv++) acc += arow[kv] * hq[kv * 384 + 2 * DA + dd];
        xno[k] = acc;
    }
    __syncthreads();

    // ---- out projection -> xcn[:, 384:]  (pipelined, 8 tiles) ----
    {
        ull accO[VV];
        #pragma unroll
        for (int v = 0; v < VV; v++) accO[v] = 0ull;
        stage16(wtA, out_w, DA, DA, 0);
        #pragma unroll 1
        for (int t = 0; t < 8; t++) {
            if (t + 1 < 8) stage16((t & 1) ? wtA : wtB, out_w, DA, DA, (t + 1) * KT);
            if (t + 1 < 8) cp_wait1(); else cp_wait0();
            __syncthreads();
            if (tid < DA)
                tile_mac16<VV>(xno, DA, t * KT, (t & 1) ? wtB : wtA, tid, accO);
            __syncthreads();
        }
        if (tid < DA) {
            float b = out_b[tid];
            #pragma unroll
            for (int v = 0; v < VV; v++) {
                float2 s = unpack2(accO[v]);
                xcn[v * DD + DM + tid] = s.x + s.y + b;
            }
        }
    }
    __syncthreads();

    // ---- rmsnorm over D=512 in place on xcn ----
    for (int v = warp; v < VV; v += 16) {
        float s = 0.f;
        for (int d = lane; d < DD; d += 32) { float t = xcn[v * DD + d]; s += t * t; }
        #pragma unroll
        for (int o = 16; o; o >>= 1) s += __shfl_xor_sync(0xffffffffu, s, o);
        float r = rsqrtf(s * (1.0f / DD) + 1e-6f);
        for (int d = lane; d < DD; d += 32) xcn[v * DD + d] *= r * nf_w[d];
    }
    __syncthreads();

    // ---- channel MLP: 2 passes of 512 hidden, pipelined 16-k weight tiles ----
    // NOTE: h1c aliases hq+xno (both dead after out projection).
    ull accB[VV];
    #pragma unroll
    for (int v = 0; v < VV; v++) accB[v] = 0ull;

    #pragma unroll 1
    for (int p = 0; p < 2; p++) {
        // phase A: hidden column j = p*512 + tid,  K=512 -> 32 tiles
        ull accA[VV];
        #pragma unroll
        for (int v = 0; v < VV; v++) accA[v] = 0ull;
        const float* gw1 = cm_w1 + (size_t)(p * 512) * DD;
        stage16(wtA, gw1, DD, 512, 0);
        #pragma unroll 1
        for (int t = 0; t < 32; t++) {
            if (t + 1 < 32) stage16((t & 1) ? wtA : wtB, gw1, DD, 512, (t + 1) * KT);
            if (t + 1 < 32) cp_wait1(); else cp_wait0();
            __syncthreads();
            tile_mac16<VV>(xcn, DD, t * KT, (t & 1) ? wtB : wtA, tid, accA);
            __syncthreads();
        }
        float b1 = cm_b1[p * 512 + tid];
        #pragma unroll
        for (int v = 0; v < VV; v++) {
            float2 s = unpack2(accA[v]);
            h1c[v * 512 + tid] = gelu_exact(s.x + s.y + b1);
        }
        // phase B: accumulate this pass's 512 k into accB (dout = tid)
        const float* gw2 = cm_w2 + p * 512;
        stage16(wtA, gw2, 2 * DD, 512, 0);
        #pragma unroll 1
        for (int t = 0; t < 32; t++) {
            if (t + 1 < 32) stage16((t & 1) ? wtA : wtB, gw2, 2 * DD, 512, (t + 1) * KT);
            if (t + 1 < 32) cp_wait1(); else cp_wait0();
            __syncthreads();      // also orders h1c writes on first iteration
            tile_mac16<VV>(h1c, 512, t * KT, (t & 1) ? wtB : wtA, tid, accB);
            __syncthreads();
        }
    }

    // ---- residual epilogue ----
    {
        float b2 = cm_b2[tid];
        float* og = out + base;
        #pragma unroll
        for (int v = 0; v < VV; v++) {
            float2 s = unpack2(accB[v]);
            og[v * DD + tid] = xs[v * DD + tid] + s.x + s.y + b2;
        }
    }
}

extern "C" void kernel_launch(void* const* d_in, const int* in_sizes, int n_in,
                              void* d_out, int out_size)
{
    const float* x     = (const float*)d_in[0];
    const float* tm_w1 = (const float*)d_in[1];
    const float* tm_b1 = (const float*)d_in[2];
    const float* tm_w2 = (const float*)d_in[3];
    const float* tm_b2 = (const float*)d_in[4];
    const float* na_w  = (const float*)d_in[5];
    const float* in_w  = (const float*)d_in[6];
    const float* in_b  = (const float*)d_in[7];
    const float* out_w = (const float*)d_in[8];
    const float* out_b = (const float*)d_in[9];
    const float* nf_w  = (const float*)d_in[10];
    const float* cm_w1 = (const float*)d_in[11];
    const float* cm_b1 = (const float*)d_in[12];
    const float* cm_w2 = (const float*)d_in[13];
    const float* cm_b2 = (const float*)d_in[14];
    float* out = (float*)d_out;

    cudaFuncSetAttribute(spatial_mixer_fused,
                         cudaFuncAttributeMaxDynamicSharedMemorySize, SMEM_BYTES);
    spatial_mixer_fused<<<BT, THREADS, SMEM_BYTES>>>(
        x, tm_w1, tm_b1, tm_w2, tm_b2, na_w, in_w, in_b, out_w, out_b,
        nf_w, cm_w1, cm_b1, cm_w2, cm_b2, out);
}

// round 5
// speedup vs baseline: 23.3209x; 4.5859x over previous
#include <cuda_runtime.h>
#include <cuda_bf16.h>
#include <math.h>

#define NN 32
#define TT 243
#define VV 17
#define DD 512
#define DM 384
#define DA 128
#define NH 4
#define HD 32
#define BT (NN*TT)
#define ROW_ELEMS (VV*DD)
#define THREADS 512
#define WR 20
#define KT 16
#define MROWS (BT*VV)            // 132192
#define MPADT 1033               // ceil(MROWS/128)
#define MPAD  (MPADT*128)        // 132224

// ---- kernel A shared memory layout (floats) ----
#define OFF_XS   0
#define OFF_XCN  (OFF_XS  + 8704)
#define OFF_HQ   (OFF_XCN + 8704)
#define OFF_XNO  (OFF_HQ  + 6528)
#define OFF_SC   (OFF_XNO + 2176)
#define OFF_WT   (OFF_SC  + 1160)
#define OFF_W1   (OFF_WT  + 2*384*WR)
#define OFF_W2   (OFF_W1  + 289)
#define OFF_B1   (OFF_W2  + 289)
#define OFF_B2   (OFF_B1  + 17)
#define SMEM_FLOATS (OFF_B2 + 17 + 4)
#define SMEM_BYTES (SMEM_FLOATS * 4)

typedef unsigned long long ull;

// ---- global scratch (static device arrays; zero-initialized) ----
__device__ __nv_bfloat16 g_xn[(size_t)MPAD * 512];
__device__ __nv_bfloat16 g_h [(size_t)MPAD * 1024];
__device__ __nv_bfloat16 g_w1[1024 * 512];
__device__ __nv_bfloat16 g_w2[512 * 1024];

__device__ __forceinline__ ull pack2(float lo, float hi) {
    ull r; asm("mov.b64 %0, {%1, %2};" : "=l"(r) : "f"(lo), "f"(hi)); return r;
}
__device__ __forceinline__ float2 unpack2(ull v) {
    float2 r; asm("mov.b64 {%0, %1}, %2;" : "=f"(r.x), "=f"(r.y) : "l"(v)); return r;
}
__device__ __forceinline__ void ffma2(ull& acc, ull a, ull b) {
    asm("fma.rn.f32x2 %0, %1, %2, %0;" : "+l"(acc) : "l"(a), "l"(b));
}
__device__ __forceinline__ float gelu_exact(float v) {
    return 0.5f * v * (1.0f + erff(v * 0.7071067811865475f));
}
__device__ __forceinline__ void cp_commit() {
    asm volatile("cp.async.commit_group;" ::: "memory");
}
__device__ __forceinline__ void cp_wait0() {
    asm volatile("cp.async.wait_group 0;" ::: "memory");
}
__device__ __forceinline__ void cp_wait1() {
    asm volatile("cp.async.wait_group 1;" ::: "memory");
}
__device__ __forceinline__ void cp_async16(unsigned dst, const void* src) {
    asm volatile("cp.async.cg.shared.global [%0], [%1], 16;" :: "r"(dst), "l"(src));
}

// ============================ KERNEL A ============================
__device__ __forceinline__ void stage16(float* __restrict__ wtb,
                                        const float* __restrict__ gw,
                                        int ldw, int nrows, int koff) {
    unsigned dstb = (unsigned)__cvta_generic_to_shared(wtb);
    const float* g = gw + koff;
    const int n4 = nrows * 4;
    #pragma unroll 1
    for (int i = threadIdx.x; i < n4; i += THREADS) {
        int j = i >> 2, c = i & 3;
        unsigned dst = dstb + (unsigned)(j * WR + c * 4) * 4u;
        const float* src = g + (size_t)j * ldw + c * 4;
        cp_async16(dst, src);
    }
    cp_commit();
}

template<int NV>
__device__ __forceinline__ void tile_mac16(const float* __restrict__ xin, int xld,
                                           int k0, const float* __restrict__ wtb,
                                           int j, ull* acc) {
    const float4* wr = (const float4*)(wtb + j * WR);
    #pragma unroll
    for (int q = 0; q < 4; q++) {
        float4 w = wr[q];
        ull w01 = pack2(w.x, w.y);
        ull w23 = pack2(w.z, w.w);
        const float* xp = xin + k0 + q * 4;
        #pragma unroll
        for (int v = 0; v < NV; v++) {
            ulonglong2 xv = *(const ulonglong2*)(xp + v * xld);
            ffma2(acc[v], xv.x, w01);
            ffma2(acc[v], xv.y, w23);
        }
    }
}

extern "C" __global__ void __launch_bounds__(THREADS, 1)
mixer_attn_kernel(const float* __restrict__ x,
                  const float* __restrict__ tm_w1, const float* __restrict__ tm_b1,
                  const float* __restrict__ tm_w2, const float* __restrict__ tm_b2,
                  const float* __restrict__ na_w,
                  const float* __restrict__ in_w,  const float* __restrict__ in_b,
                  const float* __restrict__ out_w, const float* __restrict__ out_b,
                  const float* __restrict__ nf_w)
{
    extern __shared__ float sm[];
    float* xs  = sm + OFF_XS;
    float* xcn = sm + OFF_XCN;
    float* hq  = sm + OFF_HQ;
    float* xno = sm + OFF_XNO;
    float* sc  = sm + OFF_SC;
    float* wtA = sm + OFF_WT;
    float* wtB = sm + OFF_WT + 384 * WR;
    float* w1s = sm + OFF_W1;
    float* w2s = sm + OFF_W2;
    float* b1s = sm + OFF_B1;
    float* b2s = sm + OFF_B2;

    const int tid  = threadIdx.x;
    const int warp = tid >> 5;
    const int lane = tid & 31;
    const size_t base = (size_t)blockIdx.x * ROW_ELEMS;
    const float* xg = x + base;

    for (int i = tid; i < ROW_ELEMS; i += THREADS) xs[i] = xg[i];
    for (int i = tid; i < 289; i += THREADS) { w1s[i] = tm_w1[i]; w2s[i] = tm_w2[i]; }
    if (tid < 17) { b1s[tid] = tm_b1[tid]; b2s[tid] = tm_b2[tid]; }
    __syncthreads();

    // token mixer stage 1
    for (int k = tid; k < VV * DM; k += THREADS) {
        int u = k / DM, d = k - u * DM;
        float acc = b1s[u];
        #pragma unroll
        for (int v = 0; v < VV; v++) acc += w1s[u * 17 + v] * xs[v * DD + d];
        hq[u * DM + d] = gelu_exact(acc);
    }
    __syncthreads();

    // token mixer stage 2 -> xcn[:, :384]; rmsnorm(xa) -> xno
    for (int k = tid; k < VV * DM; k += THREADS) {
        int u = k / DM, d = k - u * DM;
        float acc = b2s[u];
        #pragma unroll
        for (int v = 0; v < VV; v++) acc += w2s[u * 17 + v] * hq[v * DM + d];
        xcn[u * DD + d] = acc;
    }
    for (int v = warp; v < VV; v += 16) {
        float s = 0.f;
        for (int d = lane; d < DA; d += 32) { float t = xs[v * DD + DM + d]; s += t * t; }
        #pragma unroll
        for (int o = 16; o; o >>= 1) s += __shfl_xor_sync(0xffffffffu, s, o);
        float r = rsqrtf(s * (1.0f / DA) + 1e-6f);
        for (int d = lane; d < DA; d += 32)
            xno[v * DA + d] = xs[v * DD + DM + d] * r * na_w[d];
    }
    __syncthreads();

    // qkv
    {
        ull accQ[VV];
        #pragma unroll
        for (int v = 0; v < VV; v++) accQ[v] = 0ull;
        stage16(wtA, in_w, DA, 3 * DA, 0);
        #pragma unroll 1
        for (int t = 0; t < 8; t++) {
            if (t + 1 < 8) stage16((t & 1) ? wtA : wtB, in_w, DA, 3 * DA, (t + 1) * KT);
            if (t + 1 < 8) cp_wait1(); else cp_wait0();
            __syncthreads();
            if (tid < 3 * DA)
                tile_mac16<VV>(xno, DA, t * KT, (t & 1) ? wtB : wtA, tid, accQ);
            __syncthreads();
        }
        if (tid < 3 * DA) {
            float b = in_b[tid];
            #pragma unroll
            for (int v = 0; v < VV; v++) {
                float2 s = unpack2(accQ[v]);
                hq[v * 384 + tid] = s.x + s.y + b;
            }
        }
    }
    __syncthreads();

    // scores
    for (int k = tid; k < NH * VV * VV; k += THREADS) {
        int h = k / (VV * VV), r = k - h * VV * VV, qv = r / VV, kv = r - qv * VV;
        const float* qp = hq + qv * 384 + h * HD;
        const float* kp = hq + kv * 384 + DA + h * HD;
        float s = 0.f;
        #pragma unroll
        for (int d = 0; d < HD; d++) s += qp[d] * kp[d];
        sc[k] = s * 0.17677669529663687f;
    }
    __syncthreads();

    // softmax
    for (int r = tid; r < NH * VV; r += THREADS) {
        float* row = sc + r * VV;
        float m = row[0];
        #pragma unroll
        for (int i = 1; i < VV; i++) m = fmaxf(m, row[i]);
        float s = 0.f;
        #pragma unroll
        for (int i = 0; i < VV; i++) { float e = __expf(row[i] - m); row[i] = e; s += e; }
        float inv = 1.f / s;
        #pragma unroll
        for (int i = 0; i < VV; i++) row[i] *= inv;
    }
    __syncthreads();

    // o = attn @ v
    for (int k = tid; k < VV * DA; k += THREADS) {
        int vq = k / DA, dd = k - vq * DA, h = dd >> 5;
        const float* arow = sc + (h * VV + vq) * VV;
        float acc = 0.f;
        #pragma unroll
        for (int kv = 0; kv < VV; kv++) acc += arow[kv] * hq[kv * 384 + 2 * DA + dd];
        xno[k] = acc;
    }
    __syncthreads();

    // out projection -> xcn[:, 384:]
    {
        ull accO[VV];
        #pragma unroll
        for (int v = 0; v < VV; v++) accO[v] = 0ull;
        stage16(wtA, out_w, DA, DA, 0);
        #pragma unroll 1
        for (int t = 0; t < 8; t++) {
            if (t + 1 < 8) stage16((t & 1) ? wtA : wtB, out_w, DA, DA, (t + 1) * KT);
            if (t + 1 < 8) cp_wait1(); else cp_wait0();
            __syncthreads();
            if (tid < DA)
                tile_mac16<VV>(xno, DA, t * KT, (t & 1) ? wtB : wtA, tid, accO);
            __syncthreads();
        }
        if (tid < DA) {
            float b = out_b[tid];
            #pragma unroll
            for (int v = 0; v < VV; v++) {
                float2 s = unpack2(accO[v]);
                xcn[v * DD + DM + tid] = s.x + s.y + b;
            }
        }
    }
    __syncthreads();

    // final rmsnorm over D=512 in place on xcn
    for (int v = warp; v < VV; v += 16) {
        float s = 0.f;
        for (int d = lane; d < DD; d += 32) { float t = xcn[v * DD + d]; s += t * t; }
        #pragma unroll
        for (int o = 16; o; o >>= 1) s += __shfl_xor_sync(0xffffffffu, s, o);
        float r = rsqrtf(s * (1.0f / DD) + 1e-6f);
        for (int d = lane; d < DD; d += 32) xcn[v * DD + d] *= r * nf_w[d];
    }
    __syncthreads();

    // store normalized activations as bf16
    __nv_bfloat16* dst = g_xn + base;
    for (int i = tid; i < ROW_ELEMS; i += THREADS)
        dst[i] = __float2bfloat16(xcn[i]);
}

// ============================ WEIGHT CONVERT ============================
extern "C" __global__ void convert_weights(const float* __restrict__ w1,
                                           const float* __restrict__ w2)
{
    int i = blockIdx.x * 256 + threadIdx.x;
    if (i < 1024 * 512) g_w1[i] = __float2bfloat16(w1[i]);
    if (i < 512 * 1024) g_w2[i] = __float2bfloat16(w2[i]);
}

// ============================ BF16 GEMM ============================
__device__ __forceinline__ void ldsm4(unsigned* r, unsigned addr) {
    asm volatile("ldmatrix.sync.aligned.m8n8.x4.shared.b16 {%0,%1,%2,%3}, [%4];"
        : "=r"(r[0]), "=r"(r[1]), "=r"(r[2]), "=r"(r[3]) : "r"(addr));
}
__device__ __forceinline__ void mma16816(float* c, const unsigned* a, const unsigned* b) {
    asm volatile("mma.sync.aligned.m16n8k16.row.col.f32.bf16.bf16.f32 "
        "{%0,%1,%2,%3}, {%4,%5,%6,%7}, {%8,%9}, {%0,%1,%2,%3};"
        : "+f"(c[0]), "+f"(c[1]), "+f"(c[2]), "+f"(c[3])
        : "r"(a[0]), "r"(a[1]), "r"(a[2]), "r"(a[3]), "r"(b[0]), "r"(b[1]));
}

// C[128x128] tile of A[M x K] @ B[N x K]^T.  EPI=1: gelu(+bias)->bf16 (ldc=1024)
// EPI=2: +bias+residual->f32 (ldc=512, row-guarded).  lda = ldb = KTOT.
template<int KTOT, int EPI>
__global__ void __launch_bounds__(256, 2)
gemm_bf16(const __nv_bfloat16* __restrict__ A,
          const __nv_bfloat16* __restrict__ B,
          const float* __restrict__ bias,
          const float* __restrict__ resid,
          __nv_bfloat16* __restrict__ Cb,
          float* __restrict__ Cf)
{
    constexpr int NK = KTOT / 32;
    constexpr int SR = 40;                      // smem row stride (bf16) = 80B
    __shared__ __nv_bfloat16 sA[2][128 * SR], sB[2][128 * SR];

    const int tid  = threadIdx.x;
    const int lane = tid & 31, wid = tid >> 5;
    const int wm   = wid & 1, wn = wid >> 1;    // 2 x 4 warp grid
    const int m_blk = blockIdx.y * 128, n_blk = blockIdx.x * 128;

    const unsigned saB = (unsigned)__cvta_generic_to_shared(&sA[0][0]);
    const unsigned sbB = (unsigned)__cvta_generic_to_shared(&sB[0][0]);
    constexpr unsigned BUF = 128 * SR * 2;      // bytes per buffer

    float acc[4][4][4];
    #pragma unroll
    for (int a = 0; a < 4; a++)
        #pragma unroll
        for (int b = 0; b < 4; b++)
            #pragma unroll
            for (int c = 0; c < 4; c++) acc[a][b][c] = 0.f;

    auto load_tile = [&](int buf, int k0) {
        #pragma unroll
        for (int i = tid; i < 512; i += 256) {
            int r = i >> 2, c = i & 3;
            cp_async16(saB + buf * BUF + (unsigned)(r * SR + c * 8) * 2,
                       A + (size_t)(m_blk + r) * KTOT + k0 + c * 8);
            cp_async16(sbB + buf * BUF + (unsigned)(r * SR + c * 8) * 2,
                       B + (size_t)(n_blk + r) * KTOT + k0 + c * 8);
        }
        cp_commit();
    };

    load_tile(0, 0);
    #pragma unroll 1
    for (int kc = 0; kc < NK; kc++) {
        const int buf = kc & 1;
        if (kc + 1 < NK) { load_tile(buf ^ 1, (kc + 1) * 32); cp_wait1(); }
        else             cp_wait0();
        __syncthreads();

        #pragma unroll
        for (int ks = 0; ks < 32; ks += 16) {
            unsigned ra[4][4], rb[2][4];
            #pragma unroll
            for (int mt = 0; mt < 4; mt++)
                ldsm4(ra[mt], saB + buf * BUF +
                      (unsigned)((wm * 64 + mt * 16 + (lane & 15)) * SR +
                                 ks + (lane >> 4) * 8) * 2);
            #pragma unroll
            for (int q = 0; q < 2; q++)
                ldsm4(rb[q], sbB + buf * BUF +
                      (unsigned)((wn * 32 + q * 16 + (lane & 15)) * SR +
                                 ks + (lane >> 4) * 8) * 2);
            #pragma unroll
            for (int mt = 0; mt < 4; mt++)
                #pragma unroll
                for (int nt = 0; nt < 4; nt++) {
                    unsigned bfrag[2] = { rb[nt >> 1][nt & 1], rb[nt >> 1][(nt & 1) + 2] };
                    mma16816(acc[mt][nt], ra[mt], bfrag);
                }
        }
        __syncthreads();
    }

    // epilogue
    const int tr = lane >> 2, tc = (lane & 3) * 2;
    #pragma unroll
    for (int mt = 0; mt < 4; mt++) {
        #pragma unroll
        for (int nt = 0; nt < 4; nt++) {
            int col = n_blk + wn * 32 + nt * 8 + tc;
            float b0 = bias[col], b1 = bias[col + 1];
            #pragma unroll
            for (int h = 0; h < 2; h++) {
                int row = m_blk + wm * 64 + mt * 16 + tr + h * 8;
                float v0 = acc[mt][nt][h * 2 + 0] + b0;
                float v1 = acc[mt][nt][h * 2 + 1] + b1;
                if (EPI == 1) {
                    __nv_bfloat162 p = __floats2bfloat162_rn(gelu_exact(v0), gelu_exact(v1));
                    *reinterpret_cast<__nv_bfloat162*>(Cb + (size_t)row * 1024 + col) = p;
                } else {
                    if (row < MROWS) {
                        const float2 rx = *reinterpret_cast<const float2*>(resid + (size_t)row * 512 + col);
                        float2 o; o.x = v0 + rx.x; o.y = v1 + rx.y;
                        *reinterpret_cast<float2*>(Cf + (size_t)row * 512 + col) = o;
                    }
                }
            }
        }
    }
}

// ============================ LAUNCH ============================
extern "C" void kernel_launch(void* const* d_in, const int* in_sizes, int n_in,
                              void* d_out, int out_size)
{
    const float* x     = (const float*)d_in[0];
    const float* tm_w1 = (const float*)d_in[1];
    const float* tm_b1 = (const float*)d_in[2];
    const float* tm_w2 = (const float*)d_in[3];
    const float* tm_b2 = (const float*)d_in[4];
    const float* na_w  = (const float*)d_in[5];
    const float* in_w  = (const float*)d_in[6];
    const float* in_b  = (const float*)d_in[7];
    const float* out_w = (const float*)d_in[8];
    const float* out_b = (const float*)d_in[9];
    const float* nf_w  = (const float*)d_in[10];
    const float* cm_w1 = (const float*)d_in[11];
    const float* cm_b1 = (const float*)d_in[12];
    const float* cm_w2 = (const float*)d_in[13];
    const float* cm_b2 = (const float*)d_in[14];
    float* out = (float*)d_out;

    cudaFuncSetAttribute(mixer_attn_kernel,
                         cudaFuncAttributeMaxDynamicSharedMemorySize, SMEM_BYTES);

    convert_weights<<<(1024 * 512 + 255) / 256, 256>>>(cm_w1, cm_w2);
    mixer_attn_kernel<<<BT, THREADS, SMEM_BYTES>>>(
        x, tm_w1, tm_b1, tm_w2, tm_b2, na_w, in_w, in_b, out_w, out_b, nf_w);

    __nv_bfloat16 *p_xn, *p_h, *p_w1, *p_w2;
    cudaGetSymbolAddress((void**)&p_xn, g_xn);
    cudaGetSymbolAddress((void**)&p_h,  g_h);
    cudaGetSymbolAddress((void**)&p_w1, g_w1);
    cudaGetSymbolAddress((void**)&p_w2, g_w2);

    dim3 g1(8, MPADT), g2(4, MPADT);
    gemm_bf16<512, 1><<<g1, 256>>>(p_xn, p_w1, cm_b1, nullptr, p_h, nullptr);
    gemm_bf16<1024, 2><<<g2, 256>>>(p_h, p_w2, cm_b2, x, nullptr, out);
}

// round 6
// speedup vs baseline: 36.9405x; 1.5840x over previous
#include <cuda_runtime.h>
#include <cuda_bf16.h>
#include <math.h>

#define NN 32
#define TT 243
#define VV 17
#define DD 512
#define DM 384
#define DA 128
#define NH 4
#define HD 32
#define BT (NN*TT)               // 7776 slices
#define ROW_ELEMS (VV*DD)
#define MROWS (BT*VV)            // 132192
#define MPADT 1033
#define MPAD  (MPADT*128)

typedef unsigned long long ull;

// ---- global scratch (static device arrays; zero-initialized once) ----
__device__ __nv_bfloat16 g_xn[(size_t)MPAD * 512];    // normalized concat, bf16
__device__ __nv_bfloat16 g_h [(size_t)MPAD * 1024];   // MLP hidden, bf16
__device__ __nv_bfloat16 g_w1[1024 * 512];
__device__ __nv_bfloat16 g_w2[512 * 1024];
__device__ float g_xc[(size_t)MROWS * 512];           // concat (pre-norm), fp32
__device__ float g_xa[(size_t)MROWS * 128];           // rmsnorm(xa), fp32
__device__ float g_wqt[128 * 384];                    // in_w transposed [k][j]
__device__ float g_wot[128 * 128];                    // out_w transposed [k][j]

__device__ __forceinline__ ull pack2(float lo, float hi) {
    ull r; asm("mov.b64 %0, {%1, %2};" : "=l"(r) : "f"(lo), "f"(hi)); return r;
}
__device__ __forceinline__ float2 unpack2(ull v) {
    float2 r; asm("mov.b64 {%0, %1}, %2;" : "=f"(r.x), "=f"(r.y) : "l"(v)); return r;
}
__device__ __forceinline__ void ffma2(ull& acc, ull a, ull b) {
    asm("fma.rn.f32x2 %0, %1, %2, %0;" : "+l"(acc) : "l"(a), "l"(b));
}
__device__ __forceinline__ float gelu_exact(float v) {
    return 0.5f * v * (1.0f + erff(v * 0.7071067811865475f));
}
__device__ __forceinline__ void cp_commit() {
    asm volatile("cp.async.commit_group;" ::: "memory");
}
__device__ __forceinline__ void cp_wait0() {
    asm volatile("cp.async.wait_group 0;" ::: "memory");
}
__device__ __forceinline__ void cp_wait1() {
    asm volatile("cp.async.wait_group 1;" ::: "memory");
}
__device__ __forceinline__ void cp_async16(unsigned dst, const void* src) {
    asm volatile("cp.async.cg.shared.global [%0], [%1], 16;" :: "r"(dst), "l"(src));
}

// ==================== weight convert / transpose (once per launch) ====================
extern "C" __global__ void convert_weights(const float* __restrict__ w1,
                                           const float* __restrict__ w2,
                                           const float* __restrict__ in_w,
                                           const float* __restrict__ out_w)
{
    int i = blockIdx.x * 256 + threadIdx.x;
    if (i < 1024 * 512) g_w1[i] = __float2bfloat16(w1[i]);
    if (i < 512 * 1024) g_w2[i] = __float2bfloat16(w2[i]);
    if (i < 128 * 384) {                       // g_wqt[k*384 + j] = in_w[j*128 + k]
        int k = i / 384, j = i - k * 384;
        g_wqt[i] = in_w[j * 128 + k];
    }
    if (i < 128 * 128) {                       // g_wot[k*128 + j] = out_w[j*128 + k]
        int k = i >> 7, j = i & 127;
        g_wot[i] = out_w[j * 128 + k];
    }
}

// ==================== K1: token mixer (registers) + rmsnorm(xa) ====================
// 512 threads / slice. Threads 0..383: column d of the mixer, fully in registers.
// Warps 12..15 (threads 384..511): rmsnorm of the 17 xa rows, in parallel.
extern "C" __global__ void __launch_bounds__(512, 2)
k1_mixer(const float* __restrict__ x,
         const float* __restrict__ tm_w1, const float* __restrict__ tm_b1,
         const float* __restrict__ tm_w2, const float* __restrict__ tm_b2,
         const float* __restrict__ na_w)
{
    __shared__ float w1s[17 * 18], w2s[17 * 18], b1s[17], b2s[17];
    const int tid = threadIdx.x;
    const size_t base = (size_t)blockIdx.x * ROW_ELEMS;
    const float* xg = x + base;

    for (int i = tid; i < 289; i += 512) {
        int u = i / 17, v = i - u * 17;
        w1s[u * 18 + v] = tm_w1[i];
        w2s[u * 18 + v] = tm_w2[i];
    }
    if (tid < 17) { b1s[tid] = tm_b1[tid]; b2s[tid] = tm_b2[tid]; }
    __syncthreads();

    if (tid < DM) {
        const int d = tid;
        float xr[17];
        #pragma unroll
        for (int v = 0; v < VV; v++) xr[v] = xg[v * DD + d];
        ull xp[8];
        #pragma unroll
        for (int p = 0; p < 8; p++) xp[p] = pack2(xr[2 * p], xr[2 * p + 1]);

        float h[17];
        #pragma unroll
        for (int u = 0; u < VV; u++) {
            ull a2 = 0ull;
            const float* wr = w1s + u * 18;
            #pragma unroll
            for (int p = 0; p < 8; p++) ffma2(a2, xp[p], *(const ull*)(wr + 2 * p));
            float2 s = unpack2(a2);
            h[u] = gelu_exact(s.x + s.y + xr[16] * wr[16] + b1s[u]);
        }
        ull hp[8];
        #pragma unroll
        for (int p = 0; p < 8; p++) hp[p] = pack2(h[2 * p], h[2 * p + 1]);

        float* oc = g_xc + (size_t)blockIdx.x * VV * DD + d;
        #pragma unroll
        for (int u = 0; u < VV; u++) {
            ull a2 = 0ull;
            const float* wr = w2s + u * 18;
            #pragma unroll
            for (int p = 0; p < 8; p++) ffma2(a2, hp[p], *(const ull*)(wr + 2 * p));
            float2 s = unpack2(a2);
            oc[(size_t)u * DD] = s.x + s.y + h[16] * wr[16] + b2s[u];
        }
    } else {
        const int w4 = (tid >> 5) - 12;       // 0..3
        const int lane = tid & 31;
        for (int r = w4; r < VV; r += 4) {
            float vals[4]; float s = 0.f;
            #pragma unroll
            for (int q = 0; q < 4; q++) {
                float t = xg[r * DD + DM + lane + 32 * q];
                vals[q] = t; s += t * t;
            }
            #pragma unroll
            for (int o = 16; o; o >>= 1) s += __shfl_xor_sync(0xffffffffu, s, o);
            float rms = rsqrtf(s * (1.0f / DA) + 1e-6f);
            float* oa = g_xa + ((size_t)blockIdx.x * VV + r) * DA;
            #pragma unroll
            for (int q = 0; q < 4; q++) {
                int c = lane + 32 * q;
                oa[c] = vals[q] * rms * na_w[c];
            }
        }
    }
}

// ==================== K_att: qkv + attention + out-proj (per slice) ====================
#define QLD 388   // qkv smem row stride (floats): 388 mod 32 = 4 -> low-conflict
extern "C" __global__ void __launch_bounds__(128)
k_att(const float* __restrict__ in_b, const float* __restrict__ out_b)
{
    __shared__ float qkv_s[VV * QLD];
    __shared__ float xn_s[VV * DA];           // aliased as o_s after qkv phase
    __shared__ float sc[NH * VV * VV];

    const int tid = threadIdx.x;
    const size_t bid = blockIdx.x;
    float* o_s = xn_s;

    // load rmsnorm'd xa (17x128 fp32, contiguous)
    {
        const float* src = g_xa + bid * (VV * DA);
        #pragma unroll
        for (int i = 0; i < VV; i++) xn_s[i * DA + tid] = src[i * DA + tid];
    }
    __syncthreads();

    // qkv: col j = c*128+tid; 17 accumulators; weights coalesced LDG from g_wqt
    #pragma unroll 1
    for (int c = 0; c < 3; c++) {
        const int j = c * DA + tid;
        ull acc[17];
        #pragma unroll
        for (int v = 0; v < VV; v++) acc[v] = 0ull;
        const float* wq = g_wqt + j;
        #pragma unroll 4
        for (int p = 0; p < 64; p++) {
            float w0 = wq[(2 * p) * 384];
            float w1 = wq[(2 * p + 1) * 384];
            ull wp = pack2(w0, w1);
            const float* xb = xn_s + 2 * p;
            #pragma unroll
            for (int v = 0; v < VV; v++)
                ffma2(acc[v], *(const ull*)(xb + v * DA), wp);
        }
        float b = in_b[j];
        #pragma unroll
        for (int v = 0; v < VV; v++) {
            float2 s = unpack2(acc[v]);
            qkv_s[v * QLD + j] = s.x + s.y + b;
        }
    }
    __syncthreads();

    // scores
    for (int k = tid; k < NH * VV * VV; k += 128) {
        int h = k / (VV * VV), r = k - h * VV * VV, qv = r / VV, kv = r - qv * VV;
        const float* qp = qkv_s + qv * QLD + h * HD;
        const float* kp = qkv_s + kv * QLD + DA + h * HD;
        float s = 0.f;
        #pragma unroll
        for (int d = 0; d < HD; d++) s += qp[d] * kp[d];
        sc[k] = s * 0.17677669529663687f;
    }
    __syncthreads();

    // softmax (68 rows of 17)
    for (int r = tid; r < NH * VV; r += 128) {
        float* row = sc + r * VV;
        float m = row[0];
        #pragma unroll
        for (int i = 1; i < VV; i++) m = fmaxf(m, row[i]);
        float s = 0.f;
        #pragma unroll
        for (int i = 0; i < VV; i++) { float e = __expf(row[i] - m); row[i] = e; s += e; }
        float inv = 1.f / s;
        #pragma unroll
        for (int i = 0; i < VV; i++) row[i] *= inv;
    }
    __syncthreads();

    // o = attn @ v  -> o_s (aliases xn_s; xn fully consumed)
    {
        const int dd = tid, h = dd >> 5;
        #pragma unroll
        for (int vq = 0; vq < VV; vq++) {
            const float* arow = sc + (h * VV + vq) * VV;
            float acc = 0.f;
            #pragma unroll
            for (int kv = 0; kv < VV; kv++)
                acc += arow[kv] * qkv_s[kv * QLD + 2 * DA + dd];
            o_s[vq * DA + dd] = acc;
        }
    }
    __syncthreads();

    // out projection: col j = tid; write concat cols 384..511
    {
        const int j = tid;
        ull acc[17];
        #pragma unroll
        for (int v = 0; v < VV; v++) acc[v] = 0ull;
        const float* wo = g_wot + j;
        #pragma unroll 4
        for (int p = 0; p < 64; p++) {
            float w0 = wo[(2 * p) * 128];
            float w1 = wo[(2 * p + 1) * 128];
            ull wp = pack2(w0, w1);
            const float* ob = o_s + 2 * p;
            #pragma unroll
            for (int v = 0; v < VV; v++)
                ffma2(acc[v], *(const ull*)(ob + v * DA), wp);
        }
        float b = out_b[j];
        float* oc = g_xc + bid * (VV * DD) + DM + j;
        #pragma unroll
        for (int v = 0; v < VV; v++) {
            float2 s = unpack2(acc[v]);
            oc[(size_t)v * DD] = s.x + s.y + b;
        }
    }
}

// ==================== K_norm: rmsnorm(D=512) fp32 -> bf16 ====================
extern "C" __global__ void __launch_bounds__(256)
k_norm(const float* __restrict__ nf_w)
{
    const int warp = threadIdx.x >> 5, lane = threadIdx.x & 31;
    const size_t row = (size_t)blockIdx.x * 8 + warp;
    const float* src = g_xc + row * DD;
    float4 v[4]; float s = 0.f;
    #pragma unroll
    for (int q = 0; q < 4; q++) {
        v[q] = *(const float4*)(src + (lane + 32 * q) * 4);
        s += v[q].x * v[q].x + v[q].y * v[q].y + v[q].z * v[q].z + v[q].w * v[q].w;
    }
    #pragma unroll
    for (int o = 16; o; o >>= 1) s += __shfl_xor_sync(0xffffffffu, s, o);
    float r = rsqrtf(s * (1.0f / DD) + 1e-6f);
    __nv_bfloat16* dst = g_xn + row * DD;
    #pragma unroll
    for (int q = 0; q < 4; q++) {
        int c = (lane + 32 * q) * 4;
        const float4 wv = *(const float4*)(nf_w + c);
        __nv_bfloat162 p0 = __floats2bfloat162_rn(v[q].x * r * wv.x, v[q].y * r * wv.y);
        __nv_bfloat162 p1 = __floats2bfloat162_rn(v[q].z * r * wv.z, v[q].w * r * wv.w);
        *reinterpret_cast<__nv_bfloat162*>(dst + c)     = p0;
        *reinterpret_cast<__nv_bfloat162*>(dst + c + 2) = p1;
    }
}

// ============================ BF16 GEMM (unchanged engine) ============================
__device__ __forceinline__ void ldsm4(unsigned* r, unsigned addr) {
    asm volatile("ldmatrix.sync.aligned.m8n8.x4.shared.b16 {%0,%1,%2,%3}, [%4];"
        : "=r"(r[0]), "=r"(r[1]), "=r"(r[2]), "=r"(r[3]) : "r"(addr));
}
__device__ __forceinline__ void mma16816(float* c, const unsigned* a, const unsigned* b) {
    asm volatile("mma.sync.aligned.m16n8k16.row.col.f32.bf16.bf16.f32 "
        "{%0,%1,%2,%3}, {%4,%5,%6,%7}, {%8,%9}, {%0,%1,%2,%3};"
        : "+f"(c[0]), "+f"(c[1]), "+f"(c[2]), "+f"(c[3])
        : "r"(a[0]), "r"(a[1]), "r"(a[2]), "r"(a[3]), "r"(b[0]), "r"(b[1]));
}

template<int KTOT, int EPI>
__global__ void __launch_bounds__(256, 2)
gemm_bf16(const __nv_bfloat16* __restrict__ A,
          const __nv_bfloat16* __restrict__ B,
          const float* __restrict__ bias,
          const float* __restrict__ resid,
          __nv_bfloat16* __restrict__ Cb,
          float* __restrict__ Cf)
{
    constexpr int NK = KTOT / 32;
    constexpr int SR = 40;
    __shared__ __nv_bfloat16 sA[2][128 * SR], sB[2][128 * SR];

    const int tid  = threadIdx.x;
    const int lane = tid & 31, wid = tid >> 5;
    const int wm   = wid & 1, wn = wid >> 1;
    const int m_blk = blockIdx.y * 128, n_blk = blockIdx.x * 128;

    const unsigned saB = (unsigned)__cvta_generic_to_shared(&sA[0][0]);
    const unsigned sbB = (unsigned)__cvta_generic_to_shared(&sB[0][0]);
    constexpr unsigned BUF = 128 * SR * 2;

    float acc[4][4][4];
    #pragma unroll
    for (int a = 0; a < 4; a++)
        #pragma unroll
        for (int b = 0; b < 4; b++)
            #pragma unroll
            for (int c = 0; c < 4; c++) acc[a][b][c] = 0.f;

    auto load_tile = [&](int buf, int k0) {
        #pragma unroll
        for (int i = tid; i < 512; i += 256) {
            int r = i >> 2, c = i & 3;
            cp_async16(saB + buf * BUF + (unsigned)(r * SR + c * 8) * 2,
                       A + (size_t)(m_blk + r) * KTOT + k0 + c * 8);
            cp_async16(sbB + buf * BUF + (unsigned)(r * SR + c * 8) * 2,
                       B + (size_t)(n_blk + r) * KTOT + k0 + c * 8);
        }
        cp_commit();
    };

    load_tile(0, 0);
    #pragma unroll 1
    for (int kc = 0; kc < NK; kc++) {
        const int buf = kc & 1;
        if (kc + 1 < NK) { load_tile(buf ^ 1, (kc + 1) * 32); cp_wait1(); }
        else             cp_wait0();
        __syncthreads();

        #pragma unroll
        for (int ks = 0; ks < 32; ks += 16) {
            unsigned ra[4][4], rb[2][4];
            #pragma unroll
            for (int mt = 0; mt < 4; mt++)
                ldsm4(ra[mt], saB + buf * BUF +
                      (unsigned)((wm * 64 + mt * 16 + (lane & 15)) * SR +
                                 ks + (lane >> 4) * 8) * 2);
            #pragma unroll
            for (int q = 0; q < 2; q++)
                ldsm4(rb[q], sbB + buf * BUF +
                      (unsigned)((wn * 32 + q * 16 + (lane & 15)) * SR +
                                 ks + (lane >> 4) * 8) * 2);
            #pragma unroll
            for (int mt = 0; mt < 4; mt++)
                #pragma unroll
                for (int nt = 0; nt < 4; nt++) {
                    unsigned bfrag[2] = { rb[nt >> 1][nt & 1], rb[nt >> 1][(nt & 1) + 2] };
                    mma16816(acc[mt][nt], ra[mt], bfrag);
                }
        }
        __syncthreads();
    }

    const int tr = lane >> 2, tc = (lane & 3) * 2;
    #pragma unroll
    for (int mt = 0; mt < 4; mt++) {
        #pragma unroll
        for (int nt = 0; nt < 4; nt++) {
            int col = n_blk + wn * 32 + nt * 8 + tc;
            float b0 = bias[col], b1 = bias[col + 1];
            #pragma unroll
            for (int h = 0; h < 2; h++) {
                int row = m_blk + wm * 64 + mt * 16 + tr + h * 8;
                float v0 = acc[mt][nt][h * 2 + 0] + b0;
                float v1 = acc[mt][nt][h * 2 + 1] + b1;
                if (EPI == 1) {
                    __nv_bfloat162 p = __floats2bfloat162_rn(gelu_exact(v0), gelu_exact(v1));
                    *reinterpret_cast<__nv_bfloat162*>(Cb + (size_t)row * 1024 + col) = p;
                } else {
                    if (row < MROWS) {
                        const float2 rx = *reinterpret_cast<const float2*>(resid + (size_t)row * 512 + col);
                        float2 o; o.x = v0 + rx.x; o.y = v1 + rx.y;
                        *reinterpret_cast<float2*>(Cf + (size_t)row * 512 + col) = o;
                    }
                }
            }
        }
    }
}

// ============================ LAUNCH ============================
extern "C" void kernel_launch(void* const* d_in, const int* in_sizes, int n_in,
                              void* d_out, int out_size)
{
    const float* x     = (const float*)d_in[0];
    const float* tm_w1 = (const float*)d_in[1];
    const float* tm_b1 = (const float*)d_in[2];
    const float* tm_w2 = (const float*)d_in[3];
    const float* tm_b2 = (const float*)d_in[4];
    const float* na_w  = (const float*)d_in[5];
    const float* in_w  = (const float*)d_in[6];
    const float* in_b  = (const float*)d_in[7];
    const float* out_w = (const float*)d_in[8];
    const float* out_b = (const float*)d_in[9];
    const float* nf_w  = (const float*)d_in[10];
    const float* cm_w1 = (const float*)d_in[11];
    const float* cm_b1 = (const float*)d_in[12];
    const float* cm_w2 = (const float*)d_in[13];
    const float* cm_b2 = (const float*)d_in[14];
    float* out = (float*)d_out;

    convert_weights<<<(1024 * 512 + 255) / 256, 256>>>(cm_w1, cm_w2, in_w, out_w);
    k1_mixer<<<BT, 512>>>(x, tm_w1, tm_b1, tm_w2, tm_b2, na_w);
    k_att<<<BT, 128>>>(in_b, out_b);
    k_norm<<<MROWS / 8, 256>>>(nf_w);

    __nv_bfloat16 *p_xn, *p_h, *p_w1, *p_w2;
    cudaGetSymbolAddress((void**)&p_xn, g_xn);
    cudaGetSymbolAddress((void**)&p_h,  g_h);
    cudaGetSymbolAddress((void**)&p_w1, g_w1);
    cudaGetSymbolAddress((void**)&p_w2, g_w2);

    dim3 g1(8, MPADT), g2(4, MPADT);
    gemm_bf16<512, 1><<<g1, 256>>>(p_xn, p_w1, cm_b1, nullptr, p_h, nullptr);
    gemm_bf16<1024, 2><<<g2, 256>>>(p_h, p_w2, cm_b2, x, nullptr, out);
}

// round 7
// speedup vs baseline: 38.6346x; 1.0459x over previous
#include <cuda_runtime.h>
#include <cuda_bf16.h>
#include <math.h>

#define NN 32
#define TT 243
#define VV 17
#define DD 512
#define DM 384
#define DA 128
#define NH 4
#define HD 32
#define BT (NN*TT)               // 7776 slices
#define ROW_ELEMS (VV*DD)
#define MROWS (BT*VV)            // 132192
#define MPADT 1033
#define MPAD  (MPADT*128)

typedef unsigned long long ull;

// ---- global scratch (static device arrays; zero-initialized once) ----
__device__ __nv_bfloat16 g_xn[(size_t)MPAD * 512];    // normalized concat, bf16
__device__ __nv_bfloat16 g_h [(size_t)MPAD * 1024];   // MLP hidden, bf16
__device__ __nv_bfloat16 g_w1[1024 * 512];
__device__ __nv_bfloat16 g_w2[512 * 1024];
__device__ float g_xc[(size_t)MROWS * 512];           // concat (pre-norm), fp32
__device__ float g_xa[(size_t)MROWS * 128];           // rmsnorm(xa), fp32
__device__ float g_wqt[128 * 384];                    // in_w transposed [k][j]
__device__ float g_wot[128 * 128];                    // out_w transposed [k][j]

__device__ __forceinline__ ull pack2(float lo, float hi) {
    ull r; asm("mov.b64 %0, {%1, %2};" : "=l"(r) : "f"(lo), "f"(hi)); return r;
}
__device__ __forceinline__ float2 unpack2(ull v) {
    float2 r; asm("mov.b64 {%0, %1}, %2;" : "=f"(r.x), "=f"(r.y) : "l"(v)); return r;
}
__device__ __forceinline__ void ffma2(ull& acc, ull a, ull b) {
    asm("fma.rn.f32x2 %0, %1, %2, %0;" : "+l"(acc) : "l"(a), "l"(b));
}
__device__ __forceinline__ float gelu_exact(float v) {
    return 0.5f * v * (1.0f + erff(v * 0.7071067811865475f));
}
__device__ __forceinline__ void cp_commit() {
    asm volatile("cp.async.commit_group;" ::: "memory");
}
__device__ __forceinline__ void cp_wait0() {
    asm volatile("cp.async.wait_group 0;" ::: "memory");
}
__device__ __forceinline__ void cp_wait1() {
    asm volatile("cp.async.wait_group 1;" ::: "memory");
}
__device__ __forceinline__ void cp_async16(unsigned dst, const void* src) {
    asm volatile("cp.async.cg.shared.global [%0], [%1], 16;" :: "r"(dst), "l"(src));
}

// ==================== weight convert / transpose (once per launch) ====================
extern "C" __global__ void convert_weights(const float* __restrict__ w1,
                                           const float* __restrict__ w2,
                                           const float* __restrict__ in_w,
                                           const float* __restrict__ out_w)
{
    int i = blockIdx.x * 256 + threadIdx.x;
    if (i < 1024 * 512) g_w1[i] = __float2bfloat16(w1[i]);
    if (i < 512 * 1024) g_w2[i] = __float2bfloat16(w2[i]);
    if (i < 128 * 384) {
        int k = i / 384, j = i - k * 384;
        g_wqt[i] = in_w[j * 128 + k];
    }
    if (i < 128 * 128) {
        int k = i >> 7, j = i & 127;
        g_wot[i] = out_w[j * 128 + k];
    }
}

// ==================== K1: token mixer (registers) + rmsnorm(xa) ====================
extern "C" __global__ void __launch_bounds__(512, 2)
k1_mixer(const float* __restrict__ x,
         const float* __restrict__ tm_w1, const float* __restrict__ tm_b1,
         const float* __restrict__ tm_w2, const float* __restrict__ tm_b2,
         const float* __restrict__ na_w)
{
    __shared__ float w1s[17 * 18], w2s[17 * 18], b1s[17], b2s[17];
    const int tid = threadIdx.x;
    const size_t base = (size_t)blockIdx.x * ROW_ELEMS;
    const float* xg = x + base;

    for (int i = tid; i < 289; i += 512) {
        int u = i / 17, v = i - u * 17;
        w1s[u * 18 + v] = tm_w1[i];
        w2s[u * 18 + v] = tm_w2[i];
    }
    if (tid < 17) { b1s[tid] = tm_b1[tid]; b2s[tid] = tm_b2[tid]; }
    __syncthreads();

    if (tid < DM) {
        const int d = tid;
        float xr[17];
        #pragma unroll
        for (int v = 0; v < VV; v++) xr[v] = xg[v * DD + d];
        ull xp[8];
        #pragma unroll
        for (int p = 0; p < 8; p++) xp[p] = pack2(xr[2 * p], xr[2 * p + 1]);

        float h[17];
        #pragma unroll
        for (int u = 0; u < VV; u++) {
            ull a2 = 0ull;
            const float* wr = w1s + u * 18;
            #pragma unroll
            for (int p = 0; p < 8; p++) ffma2(a2, xp[p], *(const ull*)(wr + 2 * p));
            float2 s = unpack2(a2);
            h[u] = gelu_exact(s.x + s.y + xr[16] * wr[16] + b1s[u]);
        }
        ull hp[8];
        #pragma unroll
        for (int p = 0; p < 8; p++) hp[p] = pack2(h[2 * p], h[2 * p + 1]);

        float* oc = g_xc + (size_t)blockIdx.x * VV * DD + d;
        #pragma unroll
        for (int u = 0; u < VV; u++) {
            ull a2 = 0ull;
            const float* wr = w2s + u * 18;
            #pragma unroll
            for (int p = 0; p < 8; p++) ffma2(a2, hp[p], *(const ull*)(wr + 2 * p));
            float2 s = unpack2(a2);
            oc[(size_t)u * DD] = s.x + s.y + h[16] * wr[16] + b2s[u];
        }
    } else {
        const int w4 = (tid >> 5) - 12;
        const int lane = tid & 31;
        for (int r = w4; r < VV; r += 4) {
            float vals[4]; float s = 0.f;
            #pragma unroll
            for (int q = 0; q < 4; q++) {
                float t = xg[r * DD + DM + lane + 32 * q];
                vals[q] = t; s += t * t;
            }
            #pragma unroll
            for (int o = 16; o; o >>= 1) s += __shfl_xor_sync(0xffffffffu, s, o);
            float rms = rsqrtf(s * (1.0f / DA) + 1e-6f);
            float* oa = g_xa + ((size_t)blockIdx.x * VV + r) * DA;
            #pragma unroll
            for (int q = 0; q < 4; q++) {
                int c = lane + 32 * q;
                oa[c] = vals[q] * rms * na_w[c];
            }
        }
    }
}

// ==================== K_att: qkv + attention + out-proj (per slice) ====================
#define QLD 388
extern "C" __global__ void __launch_bounds__(128)
k_att(const float* __restrict__ in_b, const float* __restrict__ out_b)
{
    __shared__ float qkv_s[VV * QLD];
    __shared__ float xn_s[VV * DA];
    __shared__ float sc[NH * VV * VV];

    const int tid = threadIdx.x;
    const size_t bid = blockIdx.x;
    float* o_s = xn_s;

    {
        const float* src = g_xa + bid * (VV * DA);
        #pragma unroll
        for (int i = 0; i < VV; i++) xn_s[i * DA + tid] = src[i * DA + tid];
    }
    __syncthreads();

    #pragma unroll 1
    for (int c = 0; c < 3; c++) {
        const int j = c * DA + tid;
        ull acc[17];
        #pragma unroll
        for (int v = 0; v < VV; v++) acc[v] = 0ull;
        const float* wq = g_wqt + j;
        #pragma unroll 4
        for (int p = 0; p < 64; p++) {
            float w0 = wq[(2 * p) * 384];
            float w1 = wq[(2 * p + 1) * 384];
            ull wp = pack2(w0, w1);
            const float* xb = xn_s + 2 * p;
            #pragma unroll
            for (int v = 0; v < VV; v++)
                ffma2(acc[v], *(const ull*)(xb + v * DA), wp);
        }
        float b = in_b[j];
        #pragma unroll
        for (int v = 0; v < VV; v++) {
            float2 s = unpack2(acc[v]);
            qkv_s[v * QLD + j] = s.x + s.y + b;
        }
    }
    __syncthreads();

    for (int k = tid; k < NH * VV * VV; k += 128) {
        int h = k / (VV * VV), r = k - h * VV * VV, qv = r / VV, kv = r - qv * VV;
        const float* qp = qkv_s + qv * QLD + h * HD;
        const float* kp = qkv_s + kv * QLD + DA + h * HD;
        float s = 0.f;
        #pragma unroll
        for (int d = 0; d < HD; d++) s += qp[d] * kp[d];
        sc[k] = s * 0.17677669529663687f;
    }
    __syncthreads();

    for (int r = tid; r < NH * VV; r += 128) {
        float* row = sc + r * VV;
        float m = row[0];
        #pragma unroll
        for (int i = 1; i < VV; i++) m = fmaxf(m, row[i]);
        float s = 0.f;
        #pragma unroll
        for (int i = 0; i < VV; i++) { float e = __expf(row[i] - m); row[i] = e; s += e; }
        float inv = 1.f / s;
        #pragma unroll
        for (int i = 0; i < VV; i++) row[i] *= inv;
    }
    __syncthreads();

    {
        const int dd = tid, h = dd >> 5;
        #pragma unroll
        for (int vq = 0; vq < VV; vq++) {
            const float* arow = sc + (h * VV + vq) * VV;
            float acc = 0.f;
            #pragma unroll
            for (int kv = 0; kv < VV; kv++)
                acc += arow[kv] * qkv_s[kv * QLD + 2 * DA + dd];
            o_s[vq * DA + dd] = acc;
        }
    }
    __syncthreads();

    {
        const int j = tid;
        ull acc[17];
        #pragma unroll
        for (int v = 0; v < VV; v++) acc[v] = 0ull;
        const float* wo = g_wot + j;
        #pragma unroll 4
        for (int p = 0; p < 64; p++) {
            float w0 = wo[(2 * p) * 128];
            float w1 = wo[(2 * p + 1) * 128];
            ull wp = pack2(w0, w1);
            const float* ob = o_s + 2 * p;
            #pragma unroll
            for (int v = 0; v < VV; v++)
                ffma2(acc[v], *(const ull*)(ob + v * DA), wp);
        }
        float b = out_b[j];
        float* oc = g_xc + bid * (VV * DD) + DM + j;
        #pragma unroll
        for (int v = 0; v < VV; v++) {
            float2 s = unpack2(acc[v]);
            oc[(size_t)v * DD] = s.x + s.y + b;
        }
    }
}

// ==================== K_norm: rmsnorm(D=512) fp32 -> bf16 ====================
extern "C" __global__ void __launch_bounds__(256)
k_norm(const float* __restrict__ nf_w)
{
    const int warp = threadIdx.x >> 5, lane = threadIdx.x & 31;
    const size_t row = (size_t)blockIdx.x * 8 + warp;
    const float* src = g_xc + row * DD;
    float4 v[4]; float s = 0.f;
    #pragma unroll
    for (int q = 0; q < 4; q++) {
        v[q] = *(const float4*)(src + (lane + 32 * q) * 4);
        s += v[q].x * v[q].x + v[q].y * v[q].y + v[q].z * v[q].z + v[q].w * v[q].w;
    }
    #pragma unroll
    for (int o = 16; o; o >>= 1) s += __shfl_xor_sync(0xffffffffu, s, o);
    float r = rsqrtf(s * (1.0f / DD) + 1e-6f);
    __nv_bfloat16* dst = g_xn + row * DD;
    #pragma unroll
    for (int q = 0; q < 4; q++) {
        int c = (lane + 32 * q) * 4;
        const float4 wv = *(const float4*)(nf_w + c);
        __nv_bfloat162 p0 = __floats2bfloat162_rn(v[q].x * r * wv.x, v[q].y * r * wv.y);
        __nv_bfloat162 p1 = __floats2bfloat162_rn(v[q].z * r * wv.z, v[q].w * r * wv.w);
        *reinterpret_cast<__nv_bfloat162*>(dst + c)     = p0;
        *reinterpret_cast<__nv_bfloat162*>(dst + c + 2) = p1;
    }
}

// ============================ BF16 GEMM v2 ============================
// 128x128 CTA tile, K-chunk 64, 3-stage cp.async pipeline, ONE barrier/iter.
__device__ __forceinline__ void ldsm4(unsigned* r, unsigned addr) {
    asm volatile("ldmatrix.sync.aligned.m8n8.x4.shared.b16 {%0,%1,%2,%3}, [%4];"
        : "=r"(r[0]), "=r"(r[1]), "=r"(r[2]), "=r"(r[3]) : "r"(addr));
}
__device__ __forceinline__ void mma16816(float* c, const unsigned* a, const unsigned* b) {
    asm volatile("mma.sync.aligned.m16n8k16.row.col.f32.bf16.bf16.f32 "
        "{%0,%1,%2,%3}, {%4,%5,%6,%7}, {%8,%9}, {%0,%1,%2,%3};"
        : "+f"(c[0]), "+f"(c[1]), "+f"(c[2]), "+f"(c[3])
        : "r"(a[0]), "r"(a[1]), "r"(a[2]), "r"(a[3]), "r"(b[0]), "r"(b[1]));
}

#define KC 64                       // k per stage
#define SRG 72                      // smem row stride (bf16): 144B, 16B-aligned,
                                    // conflict-free ldmatrix (144 = 128 + 16)
#define TILE_B ((unsigned)(128 * SRG * 2))        // one matrix tile, bytes
#define STAGE_B (2u * TILE_B)                     // A + B per stage
#define GSMEM_BYTES (3 * 2 * 128 * SRG * 2)       // 110,592 B

template<int KTOT, int EPI>
__global__ void __launch_bounds__(256, 2)
gemm_bf16(const __nv_bfloat16* __restrict__ A,
          const __nv_bfloat16* __restrict__ B,
          const float* __restrict__ bias,
          const float* __restrict__ resid,
          __nv_bfloat16* __restrict__ Cb,
          float* __restrict__ Cf)
{
    constexpr int NT = KTOT / KC;
    extern __shared__ __nv_bfloat16 gsm[];

    const int tid  = threadIdx.x;
    const int lane = tid & 31, wid = tid >> 5;
    const int wm   = wid & 1, wn = wid >> 1;
    const int m_blk = blockIdx.y * 128, n_blk = blockIdx.x * 128;
    const unsigned sbase = (unsigned)__cvta_generic_to_shared(gsm);

    float acc[4][4][4];
    #pragma unroll
    for (int a = 0; a < 4; a++)
        #pragma unroll
        for (int b = 0; b < 4; b++)
            #pragma unroll
            for (int c = 0; c < 4; c++) acc[a][b][c] = 0.f;

    auto load_tile = [&](int st, int k0) {
        const unsigned sa = sbase + st * STAGE_B;
        const unsigned sb = sa + TILE_B;
        #pragma unroll
        for (int i = tid; i < 1024; i += 256) {
            int r = i >> 3, c = i & 7;                    // c*8 elems = 16B chunk
            unsigned off = (unsigned)(r * SRG + c * 8) * 2;
            cp_async16(sa + off, A + (size_t)(m_blk + r) * KTOT + k0 + c * 8);
            cp_async16(sb + off, B + (size_t)(n_blk + r) * KTOT + k0 + c * 8);
        }
        cp_commit();
    };

    load_tile(0, 0);
    if (NT > 1) load_tile(1, KC);

    #pragma unroll 1
    for (int t = 0; t < NT; t++) {
        if (t + 1 < NT) cp_wait1(); else cp_wait0();
        __syncthreads();                                  // all compute(t-1) done
        if (t + 2 < NT) load_tile((t + 2) % 3, (t + 2) * KC);

        const unsigned sa = sbase + (t % 3) * STAGE_B;
        const unsigned sb = sa + TILE_B;
        #pragma unroll
        for (int ks = 0; ks < KC; ks += 16) {
            unsigned ra[4][4], rb[2][4];
            #pragma unroll
            for (int mt = 0; mt < 4; mt++)
                ldsm4(ra[mt], sa + (unsigned)((wm * 64 + mt * 16 + (lane & 15)) * SRG +
                                              ks + (lane >> 4) * 8) * 2);
            #pragma unroll
            for (int q = 0; q < 2; q++)
                ldsm4(rb[q], sb + (unsigned)((wn * 32 + q * 16 + (lane & 15)) * SRG +
                                             ks + (lane >> 4) * 8) * 2);
            #pragma unroll
            for (int mt = 0; mt < 4; mt++)
                #pragma unroll
                for (int nt = 0; nt < 4; nt++) {
                    unsigned bfrag[2] = { rb[nt >> 1][nt & 1], rb[nt >> 1][(nt & 1) + 2] };
                    mma16816(acc[mt][nt], ra[mt], bfrag);
                }
        }
    }

    const int tr = lane >> 2, tc = (lane & 3) * 2;
    #pragma unroll
    for (int mt = 0; mt < 4; mt++) {
        #pragma unroll
        for (int nt = 0; nt < 4; nt++) {
            int col = n_blk + wn * 32 + nt * 8 + tc;
            float b0 = bias[col], b1 = bias[col + 1];
            #pragma unroll
            for (int h = 0; h < 2; h++) {
                int row = m_blk + wm * 64 + mt * 16 + tr + h * 8;
                float v0 = acc[mt][nt][h * 2 + 0] + b0;
                float v1 = acc[mt][nt][h * 2 + 1] + b1;
                if (EPI == 1) {
                    __nv_bfloat162 p = __floats2bfloat162_rn(gelu_exact(v0), gelu_exact(v1));
                    *reinterpret_cast<__nv_bfloat162*>(Cb + (size_t)row * 1024 + col) = p;
                } else {
                    if (row < MROWS) {
                        const float2 rx = *reinterpret_cast<const float2*>(resid + (size_t)row * 512 + col);
                        float2 o; o.x = v0 + rx.x; o.y = v1 + rx.y;
                        *reinterpret_cast<float2*>(Cf + (size_t)row * 512 + col) = o;
                    }
                }
            }
        }
    }
}

// ============================ LAUNCH ============================
extern "C" void kernel_launch(void* const* d_in, const int* in_sizes, int n_in,
                              void* d_out, int out_size)
{
    const float* x     = (const float*)d_in[0];
    const float* tm_w1 = (const float*)d_in[1];
    const float* tm_b1 = (const float*)d_in[2];
    const float* tm_w2 = (const float*)d_in[3];
    const float* tm_b2 = (const float*)d_in[4];
    const float* na_w  = (const float*)d_in[5];
    const float* in_w  = (const float*)d_in[6];
    const float* in_b  = (const float*)d_in[7];
    const float* out_w = (const float*)d_in[8];
    const float* out_b = (const float*)d_in[9];
    const float* nf_w  = (const float*)d_in[10];
    const float* cm_w1 = (const float*)d_in[11];
    const float* cm_b1 = (const float*)d_in[12];
    const float* cm_w2 = (const float*)d_in[13];
    const float* cm_b2 = (const float*)d_in[14];
    float* out = (float*)d_out;

    static bool attr_set = false;
    if (!attr_set) {
        cudaFuncSetAttribute(gemm_bf16<512, 1>,
                             cudaFuncAttributeMaxDynamicSharedMemorySize, GSMEM_BYTES);
        cudaFuncSetAttribute(gemm_bf16<1024, 2>,
                             cudaFuncAttributeMaxDynamicSharedMemorySize, GSMEM_BYTES);
        attr_set = true;
    }

    convert_weights<<<(1024 * 512 + 255) / 256, 256>>>(cm_w1, cm_w2, in_w, out_w);
    k1_mixer<<<BT, 512>>>(x, tm_w1, tm_b1, tm_w2, tm_b2, na_w);
    k_att<<<BT, 128>>>(in_b, out_b);
    k_norm<<<MROWS / 8, 256>>>(nf_w);

    __nv_bfloat16 *p_xn, *p_h, *p_w1, *p_w2;
    cudaGetSymbolAddress((void**)&p_xn, g_xn);
    cudaGetSymbolAddress((void**)&p_h,  g_h);
    cudaGetSymbolAddress((void**)&p_w1, g_w1);
    cudaGetSymbolAddress((void**)&p_w2, g_w2);

    dim3 g1(8, MPADT), g2(4, MPADT);
    gemm_bf16<512, 1><<<g1, 256, GSMEM_BYTES>>>(p_xn, p_w1, cm_b1, nullptr, p_h, nullptr);
    gemm_bf16<1024, 2><<<g2, 256, GSMEM_BYTES>>>(p_h, p_w2, cm_b2, x, nullptr, out);
}

// round 8
// speedup vs baseline: 48.7792x; 1.2626x over previous
#include <cuda_runtime.h>
#include <cuda_bf16.h>
#include <math.h>

#define NN 32
#define TT 243
#define VV 17
#define DD 512
#define DM 384
#define DA 128
#define NH 4
#define HD 32
#define BT (NN*TT)               // 7776 slices
#define ROW_ELEMS (VV*DD)
#define MROWS (BT*VV)            // 132192
#define MPADT 1033
#define MPAD  (MPADT*128)

typedef unsigned long long ull;

// ---- global scratch (static device arrays; zero-initialized) ----
__device__ __nv_bfloat16 g_xn [(size_t)MPAD * 512];   // normalized concat, bf16
__device__ __nv_bfloat16 g_h  [(size_t)MPAD * 1024];  // MLP hidden, bf16
__device__ __nv_bfloat16 g_w1 [1024 * 512];
__device__ __nv_bfloat16 g_w2 [512 * 1024];
__device__ float         g_xc [(size_t)MROWS * 512];  // concat (pre-norm), fp32
__device__ __nv_bfloat16 g_xa [(size_t)MPAD * 128];   // rmsnorm(xa), bf16 (pad rows 0)
__device__ float         g_qkv[(size_t)MPAD * 384];   // qkv projections, fp32
__device__ __nv_bfloat16 g_o  [(size_t)MPAD * 128];   // attention output, bf16
__device__ __nv_bfloat16 g_wqb[384 * 128];            // in_w as bf16 (B layout)
__device__ __nv_bfloat16 g_wob[128 * 128];            // out_w as bf16

__device__ __forceinline__ ull pack2(float lo, float hi) {
    ull r; asm("mov.b64 %0, {%1, %2};" : "=l"(r) : "f"(lo), "f"(hi)); return r;
}
__device__ __forceinline__ float2 unpack2(ull v) {
    float2 r; asm("mov.b64 {%0, %1}, %2;" : "=f"(r.x), "=f"(r.y) : "l"(v)); return r;
}
__device__ __forceinline__ void ffma2(ull& acc, ull a, ull b) {
    asm("fma.rn.f32x2 %0, %1, %2, %0;" : "+l"(acc) : "l"(a), "l"(b));
}
__device__ __forceinline__ float gelu_exact(float v) {
    return 0.5f * v * (1.0f + erff(v * 0.7071067811865475f));
}
__device__ __forceinline__ void cp_commit() {
    asm volatile("cp.async.commit_group;" ::: "memory");
}
__device__ __forceinline__ void cp_wait0() {
    asm volatile("cp.async.wait_group 0;" ::: "memory");
}
__device__ __forceinline__ void cp_wait1() {
    asm volatile("cp.async.wait_group 1;" ::: "memory");
}
__device__ __forceinline__ void cp_async16(unsigned dst, const void* src) {
    asm volatile("cp.async.cg.shared.global [%0], [%1], 16;" :: "r"(dst), "l"(src));
}

// ==================== weight convert (once per launch) ====================
extern "C" __global__ void convert_weights(const float* __restrict__ w1,
                                           const float* __restrict__ w2,
                                           const float* __restrict__ in_w,
                                           const float* __restrict__ out_w)
{
    int i = blockIdx.x * 256 + threadIdx.x;
    if (i < 1024 * 512) g_w1[i] = __float2bfloat16(w1[i]);
    if (i < 512 * 1024) g_w2[i] = __float2bfloat16(w2[i]);
    if (i < 384 * 128)  g_wqb[i] = __float2bfloat16(in_w[i]);
    if (i < 128 * 128)  g_wob[i] = __float2bfloat16(out_w[i]);
}

// ==================== K1: token mixer (registers) + rmsnorm(xa) ====================
extern "C" __global__ void __launch_bounds__(512, 2)
k1_mixer(const float* __restrict__ x,
         const float* __restrict__ tm_w1, const float* __restrict__ tm_b1,
         const float* __restrict__ tm_w2, const float* __restrict__ tm_b2,
         const float* __restrict__ na_w)
{
    __shared__ float w1s[17 * 18], w2s[17 * 18], b1s[17], b2s[17];
    const int tid = threadIdx.x;
    const size_t base = (size_t)blockIdx.x * ROW_ELEMS;
    const float* xg = x + base;

    for (int i = tid; i < 289; i += 512) {
        int u = i / 17, v = i - u * 17;
        w1s[u * 18 + v] = tm_w1[i];
        w2s[u * 18 + v] = tm_w2[i];
    }
    if (tid < 17) { b1s[tid] = tm_b1[tid]; b2s[tid] = tm_b2[tid]; }
    __syncthreads();

    if (tid < DM) {
        const int d = tid;
        float xr[17];
        #pragma unroll
        for (int v = 0; v < VV; v++) xr[v] = xg[v * DD + d];
        ull xp[8];
        #pragma unroll
        for (int p = 0; p < 8; p++) xp[p] = pack2(xr[2 * p], xr[2 * p + 1]);

        float h[17];
        #pragma unroll
        for (int u = 0; u < VV; u++) {
            ull a2 = 0ull;
            const float* wr = w1s + u * 18;
            #pragma unroll
            for (int p = 0; p < 8; p++) ffma2(a2, xp[p], *(const ull*)(wr + 2 * p));
            float2 s = unpack2(a2);
            h[u] = gelu_exact(s.x + s.y + xr[16] * wr[16] + b1s[u]);
        }
        ull hp[8];
        #pragma unroll
        for (int p = 0; p < 8; p++) hp[p] = pack2(h[2 * p], h[2 * p + 1]);

        float* oc = g_xc + (size_t)blockIdx.x * VV * DD + d;
        #pragma unroll
        for (int u = 0; u < VV; u++) {
            ull a2 = 0ull;
            const float* wr = w2s + u * 18;
            #pragma unroll
            for (int p = 0; p < 8; p++) ffma2(a2, hp[p], *(const ull*)(wr + 2 * p));
            float2 s = unpack2(a2);
            oc[(size_t)u * DD] = s.x + s.y + h[16] * wr[16] + b2s[u];
        }
    } else {
        const int w4 = (tid >> 5) - 12;
        const int lane = tid & 31;
        for (int r = w4; r < VV; r += 4) {
            float vals[4]; float s = 0.f;
            #pragma unroll
            for (int q = 0; q < 4; q++) {
                float t = xg[r * DD + DM + lane + 32 * q];
                vals[q] = t; s += t * t;
            }
            #pragma unroll
            for (int o = 16; o; o >>= 1) s += __shfl_xor_sync(0xffffffffu, s, o);
            float rms = rsqrtf(s * (1.0f / DA) + 1e-6f);
            __nv_bfloat16* oa = g_xa + ((size_t)blockIdx.x * VV + r) * DA;
            #pragma unroll
            for (int q = 0; q < 4; q++) {
                int c = lane + 32 * q;
                oa[c] = __float2bfloat16(vals[q] * rms * na_w[c]);
            }
        }
    }
}

// ==================== K_att2: scores + softmax + o (per slice) ====================
#define QLD 388
extern "C" __global__ void __launch_bounds__(128)
k_att2()
{
    __shared__ float qkv_s[VV * QLD];
    __shared__ float sc[NH * VV * VV];

    const int tid = threadIdx.x;
    const size_t bid = blockIdx.x;

    // load qkv rows (17 x 384 fp32) via float4
    {
        const float* src = g_qkv + bid * (VV * 384);
        #pragma unroll 4
        for (int i = tid; i < VV * 96; i += 128) {
            int v = i / 96, c = i - v * 96;
            *(float4*)(qkv_s + v * QLD + c * 4) = *(const float4*)(src + v * 384 + c * 4);
        }
    }
    __syncthreads();

    // scores
    for (int k = tid; k < NH * VV * VV; k += 128) {
        int h = k / (VV * VV), r = k - h * VV * VV, qv = r / VV, kv = r - qv * VV;
        const float* qp = qkv_s + qv * QLD + h * HD;
        const float* kp = qkv_s + kv * QLD + DA + h * HD;
        float s = 0.f;
        #pragma unroll
        for (int d = 0; d < HD; d++) s += qp[d] * kp[d];
        sc[k] = s * 0.17677669529663687f;
    }
    __syncthreads();

    // softmax (68 rows of 17)
    for (int r = tid; r < NH * VV; r += 128) {
        float* row = sc + r * VV;
        float m = row[0];
        #pragma unroll
        for (int i = 1; i < VV; i++) m = fmaxf(m, row[i]);
        float s = 0.f;
        #pragma unroll
        for (int i = 0; i < VV; i++) { float e = __expf(row[i] - m); row[i] = e; s += e; }
        float inv = 1.f / s;
        #pragma unroll
        for (int i = 0; i < VV; i++) row[i] *= inv;
    }
    __syncthreads();

    // o = attn @ v -> bf16 global
    {
        const int dd = tid, h = dd >> 5;
        __nv_bfloat16* og = g_o + bid * (VV * DA) + dd;
        #pragma unroll
        for (int vq = 0; vq < VV; vq++) {
            const float* arow = sc + (h * VV + vq) * VV;
            float acc = 0.f;
            #pragma unroll
            for (int kv = 0; kv < VV; kv++)
                acc += arow[kv] * qkv_s[kv * QLD + 2 * DA + dd];
            og[(size_t)vq * DA] = __float2bfloat16(acc);
        }
    }
}

// ==================== K_norm: rmsnorm(D=512) fp32 -> bf16 ====================
extern "C" __global__ void __launch_bounds__(256)
k_norm(const float* __restrict__ nf_w)
{
    const int warp = threadIdx.x >> 5, lane = threadIdx.x & 31;
    const size_t row = (size_t)blockIdx.x * 8 + warp;
    const float* src = g_xc + row * DD;
    float4 v[4]; float s = 0.f;
    #pragma unroll
    for (int q = 0; q < 4; q++) {
        v[q] = *(const float4*)(src + (lane + 32 * q) * 4);
        s += v[q].x * v[q].x + v[q].y * v[q].y + v[q].z * v[q].z + v[q].w * v[q].w;
    }
    #pragma unroll
    for (int o = 16; o; o >>= 1) s += __shfl_xor_sync(0xffffffffu, s, o);
    float r = rsqrtf(s * (1.0f / DD) + 1e-6f);
    __nv_bfloat16* dst = g_xn + row * DD;
    #pragma unroll
    for (int q = 0; q < 4; q++) {
        int c = (lane + 32 * q) * 4;
        const float4 wv = *(const float4*)(nf_w + c);
        __nv_bfloat162 p0 = __floats2bfloat162_rn(v[q].x * r * wv.x, v[q].y * r * wv.y);
        __nv_bfloat162 p1 = __floats2bfloat162_rn(v[q].z * r * wv.z, v[q].w * r * wv.w);
        *reinterpret_cast<__nv_bfloat162*>(dst + c)     = p0;
        *reinterpret_cast<__nv_bfloat162*>(dst + c + 2) = p1;
    }
}

// ============================ BF16 GEMM v3 ============================
// 128x128 CTA tile, KC=64, 3-stage cp.async pipeline, 1 barrier/iter,
// register-fragment double buffering across k-steps.
__device__ __forceinline__ void ldsm4(unsigned* r, unsigned addr) {
    asm volatile("ldmatrix.sync.aligned.m8n8.x4.shared.b16 {%0,%1,%2,%3}, [%4];"
        : "=r"(r[0]), "=r"(r[1]), "=r"(r[2]), "=r"(r[3]) : "r"(addr));
}
__device__ __forceinline__ void mma16816(float* c, const unsigned* a, const unsigned* b) {
    asm volatile("mma.sync.aligned.m16n8k16.row.col.f32.bf16.bf16.f32 "
        "{%0,%1,%2,%3}, {%4,%5,%6,%7}, {%8,%9}, {%0,%1,%2,%3};"
        : "+f"(c[0]), "+f"(c[1]), "+f"(c[2]), "+f"(c[3])
        : "r"(a[0]), "r"(a[1]), "r"(a[2]), "r"(a[3]), "r"(b[0]), "r"(b[1]));
}

#define KC 64
#define SRG 72
#define TILE_B ((unsigned)(128 * SRG * 2))
#define STAGE_B (2u * TILE_B)
#define GSMEM_BYTES (3 * 2 * 128 * SRG * 2)       // 110,592 B

// EPI: 1 = gelu(+bias) -> bf16, ldc 1024 (no guard; C padded)
//      2 = +bias+residual -> f32, ldc 512, row-guarded
//      3 = +bias -> f32, ldc 384 (no guard; C padded)
//      4 = +bias -> f32, ldc 512, row-guarded (C pre-offset)
template<int KTOT, int EPI>
__global__ void __launch_bounds__(256, 2)
gemm_bf16(const __nv_bfloat16* __restrict__ A,
          const __nv_bfloat16* __restrict__ B,
          const float* __restrict__ bias,
          const float* __restrict__ resid,
          __nv_bfloat16* __restrict__ Cb,
          float* __restrict__ Cf)
{
    constexpr int NT = KTOT / KC;
    extern __shared__ __nv_bfloat16 gsm[];

    const int tid  = threadIdx.x;
    const int lane = tid & 31, wid = tid >> 5;
    const int wm   = wid & 1, wn = wid >> 1;
    const int m_blk = blockIdx.y * 128, n_blk = blockIdx.x * 128;
    const unsigned sbase = (unsigned)__cvta_generic_to_shared(gsm);

    float acc[4][4][4];
    #pragma unroll
    for (int a = 0; a < 4; a++)
        #pragma unroll
        for (int b = 0; b < 4; b++)
            #pragma unroll
            for (int c = 0; c < 4; c++) acc[a][b][c] = 0.f;

    auto load_tile = [&](int st, int k0) {
        const unsigned sa = sbase + st * STAGE_B;
        const unsigned sb = sa + TILE_B;
        #pragma unroll
        for (int i = tid; i < 1024; i += 256) {
            int r = i >> 3, c = i & 7;
            unsigned off = (unsigned)(r * SRG + c * 8) * 2;
            cp_async16(sa + off, A + (size_t)(m_blk + r) * KTOT + k0 + c * 8);
            cp_async16(sb + off, B + (size_t)(n_blk + r) * KTOT + k0 + c * 8);
        }
        cp_commit();
    };

    load_tile(0, 0);
    if (NT > 1) load_tile(1, KC);

    #pragma unroll 1
    for (int t = 0; t < NT; t++) {
        if (t + 1 < NT) cp_wait1(); else cp_wait0();
        __syncthreads();
        if (t + 2 < NT) load_tile((t + 2) % 3, (t + 2) * KC);

        const unsigned sa = sbase + (t % 3) * STAGE_B;
        const unsigned sb = sa + TILE_B;

        unsigned ra[2][4][4], rb[2][2][4];
        auto ldf = [&](int ks, int pb) {
            #pragma unroll
            for (int mt = 0; mt < 4; mt++)
                ldsm4(ra[pb][mt], sa + (unsigned)((wm * 64 + mt * 16 + (lane & 15)) * SRG +
                                                  ks + (lane >> 4) * 8) * 2);
            #pragma unroll
            for (int q = 0; q < 2; q++)
                ldsm4(rb[pb][q], sb + (unsigned)((wn * 32 + q * 16 + (lane & 15)) * SRG +
                                                 ks + (lane >> 4) * 8) * 2);
        };

        ldf(0, 0);
        #pragma unroll
        for (int ksi = 0; ksi < KC / 16; ksi++) {
            if (ksi + 1 < KC / 16) ldf((ksi + 1) * 16, (ksi + 1) & 1);
            const int pb = ksi & 1;
            #pragma unroll
            for (int mt = 0; mt < 4; mt++)
                #pragma unroll
                for (int nt = 0; nt < 4; nt++) {
                    unsigned bfrag[2] = { rb[pb][nt >> 1][nt & 1],
                                          rb[pb][nt >> 1][(nt & 1) + 2] };
                    mma16816(acc[mt][nt], ra[pb][mt], bfrag);
                }
        }
    }

    const int tr = lane >> 2, tc = (lane & 3) * 2;
    #pragma unroll
    for (int mt = 0; mt < 4; mt++) {
        #pragma unroll
        for (int nt = 0; nt < 4; nt++) {
            int col = n_blk + wn * 32 + nt * 8 + tc;
            float b0 = bias[col], b1 = bias[col + 1];
            #pragma unroll
            for (int h = 0; h < 2; h++) {
                int row = m_blk + wm * 64 + mt * 16 + tr + h * 8;
                float v0 = acc[mt][nt][h * 2 + 0] + b0;
                float v1 = acc[mt][nt][h * 2 + 1] + b1;
                if (EPI == 1) {
                    __nv_bfloat162 p = __floats2bfloat162_rn(gelu_exact(v0), gelu_exact(v1));
                    *reinterpret_cast<__nv_bfloat162*>(Cb + (size_t)row * 1024 + col) = p;
                } else if (EPI == 2) {
                    if (row < MROWS) {
                        const float2 rx = *reinterpret_cast<const float2*>(resid + (size_t)row * 512 + col);
                        float2 o; o.x = v0 + rx.x; o.y = v1 + rx.y;
                        *reinterpret_cast<float2*>(Cf + (size_t)row * 512 + col) = o;
                    }
                } else if (EPI == 3) {
                    float2 o; o.x = v0; o.y = v1;
                    *reinterpret_cast<float2*>(Cf + (size_t)row * 384 + col) = o;
                } else {
                    if (row < MROWS) {
                        float2 o; o.x = v0; o.y = v1;
                        *reinterpret_cast<float2*>(Cf + (size_t)row * 512 + col) = o;
                    }
                }
            }
        }
    }
}

// ============================ LAUNCH ============================
extern "C" void kernel_launch(void* const* d_in, const int* in_sizes, int n_in,
                              void* d_out, int out_size)
{
    const float* x     = (const float*)d_in[0];
    const float* tm_w1 = (const float*)d_in[1];
    const float* tm_b1 = (const float*)d_in[2];
    const float* tm_w2 = (const float*)d_in[3];
    const float* tm_b2 = (const float*)d_in[4];
    const float* na_w  = (const float*)d_in[5];
    const float* in_w  = (const float*)d_in[6];
    const float* in_b  = (const float*)d_in[7];
    const float* out_w = (const float*)d_in[8];
    const float* out_b = (const float*)d_in[9];
    const float* nf_w  = (const float*)d_in[10];
    const float* cm_w1 = (const float*)d_in[11];
    const float* cm_b1 = (const float*)d_in[12];
    const float* cm_w2 = (const float*)d_in[13];
    const float* cm_b2 = (const float*)d_in[14];
    float* out = (float*)d_out;

    static bool attr_set = false;
    if (!attr_set) {
        cudaFuncSetAttribute(gemm_bf16<512, 1>,
                             cudaFuncAttributeMaxDynamicSharedMemorySize, GSMEM_BYTES);
        cudaFuncSetAttribute(gemm_bf16<1024, 2>,
                             cudaFuncAttributeMaxDynamicSharedMemorySize, GSMEM_BYTES);
        cudaFuncSetAttribute(gemm_bf16<128, 3>,
                             cudaFuncAttributeMaxDynamicSharedMemorySize, GSMEM_BYTES);
        cudaFuncSetAttribute(gemm_bf16<128, 4>,
                             cudaFuncAttributeMaxDynamicSharedMemorySize, GSMEM_BYTES);
        attr_set = true;
    }

    __nv_bfloat16 *p_xn, *p_h, *p_w1, *p_w2, *p_xa, *p_o, *p_wqb, *p_wob;
    float *p_qkv, *p_xc;
    cudaGetSymbolAddress((void**)&p_xn,  g_xn);
    cudaGetSymbolAddress((void**)&p_h,   g_h);
    cudaGetSymbolAddress((void**)&p_w1,  g_w1);
    cudaGetSymbolAddress((void**)&p_w2,  g_w2);
    cudaGetSymbolAddress((void**)&p_xa,  g_xa);
    cudaGetSymbolAddress((void**)&p_o,   g_o);
    cudaGetSymbolAddress((void**)&p_wqb, g_wqb);
    cudaGetSymbolAddress((void**)&p_wob, g_wob);
    cudaGetSymbolAddress((void**)&p_qkv, g_qkv);
    cudaGetSymbolAddress((void**)&p_xc,  g_xc);

    convert_weights<<<2048, 256>>>(cm_w1, cm_w2, in_w, out_w);
    k1_mixer<<<BT, 512>>>(x, tm_w1, tm_b1, tm_w2, tm_b2, na_w);

    dim3 gq(3, MPADT);
    gemm_bf16<128, 3><<<gq, 256, GSMEM_BYTES>>>(p_xa, p_wqb, in_b, nullptr, nullptr, p_qkv);
    k_att2<<<BT, 128>>>();
    dim3 go(1, MPADT);
    gemm_bf16<128, 4><<<go, 256, GSMEM_BYTES>>>(p_o, p_wob, out_b, nullptr, nullptr, p_xc + DM);

    k_norm<<<MROWS / 8, 256>>>(nf_w);

    dim3 g1(8, MPADT), g2(4, MPADT);
    gemm_bf16<512, 1><<<g1, 256, GSMEM_BYTES>>>(p_xn, p_w1, cm_b1, nullptr, p_h, nullptr);
    gemm_bf16<1024, 2><<<g2, 256, GSMEM_BYTES>>>(p_h, p_w2, cm_b2, x, nullptr, out);
}

// round 11
// speedup vs baseline: 50.1272x; 1.0276x over previous
#include <cuda_runtime.h>
#include <cuda_bf16.h>
#include <cstdint>
#include <math.h>

#define NN 32
#define TT 243
#define VV 17
#define DD 512
#define DM 384
#define DA 128
#define NH 4
#define HD 32
#define BT (NN*TT)               // 7776 slices
#define ROW_ELEMS (VV*DD)
#define MROWS (BT*VV)            // 132192
#define MPADT 1033
#define MPAD  (MPADT*128)

typedef unsigned long long ull;

// ---- global scratch (static device arrays; zero-initialized) ----
__device__ __nv_bfloat16 g_xn [(size_t)MPAD * 512];
__device__ __nv_bfloat16 g_h  [(size_t)MPAD * 1024];
__device__ __nv_bfloat16 g_w1 [1024 * 512];
__device__ __nv_bfloat16 g_w2 [512 * 1024];
__device__ float         g_xc [(size_t)MROWS * 512];
__device__ __nv_bfloat16 g_xa [(size_t)MPAD * 128];
__device__ float         g_qkv[(size_t)MPAD * 384];
__device__ __nv_bfloat16 g_o  [(size_t)MPAD * 128];
__device__ __nv_bfloat16 g_wqb[384 * 128];
__device__ __nv_bfloat16 g_wob[128 * 128];

__device__ __forceinline__ ull pack2(float lo, float hi) {
    ull r; asm("mov.b64 %0, {%1, %2};" : "=l"(r) : "f"(lo), "f"(hi)); return r;
}
__device__ __forceinline__ float2 unpack2(ull v) {
    float2 r; asm("mov.b64 {%0, %1}, %2;" : "=f"(r.x), "=f"(r.y) : "l"(v)); return r;
}
__device__ __forceinline__ void ffma2(ull& acc, ull a, ull b) {
    asm("fma.rn.f32x2 %0, %1, %2, %0;" : "+l"(acc) : "l"(a), "l"(b));
}
__device__ __forceinline__ float gelu_exact(float v) {
    return 0.5f * v * (1.0f + erff(v * 0.7071067811865475f));
}
__device__ __forceinline__ void cp_commit() {
    asm volatile("cp.async.commit_group;" ::: "memory");
}
__device__ __forceinline__ void cp_wait0() { asm volatile("cp.async.wait_group 0;" ::: "memory"); }
__device__ __forceinline__ void cp_wait1() { asm volatile("cp.async.wait_group 1;" ::: "memory"); }
__device__ __forceinline__ void cp_async16(unsigned dst, const void* src) {
    asm volatile("cp.async.cg.shared.global [%0], [%1], 16;" :: "r"(dst), "l"(src));
}

// ==================== weight convert ====================
extern "C" __global__ void convert_weights(const float* __restrict__ w1,
                                           const float* __restrict__ w2,
                                           const float* __restrict__ in_w,
                                           const float* __restrict__ out_w)
{
    int i = blockIdx.x * 256 + threadIdx.x;
    if (i < 1024 * 512) g_w1[i] = __float2bfloat16(w1[i]);
    if (i < 512 * 1024) g_w2[i] = __float2bfloat16(w2[i]);
    if (i < 384 * 128)  g_wqb[i] = __float2bfloat16(in_w[i]);
    if (i < 128 * 128)  g_wob[i] = __float2bfloat16(out_w[i]);
}

// ==================== K1a: token mixer (registers), 384 threads ====================
extern "C" __global__ void __launch_bounds__(384, 2)
k1_mix(const float* __restrict__ x,
       const float* __restrict__ tm_w1, const float* __restrict__ tm_b1,
       const float* __restrict__ tm_w2, const float* __restrict__ tm_b2)
{
    __shared__ float w1s[17 * 18], w2s[17 * 18], b1s[17], b2s[17];
    const int tid = threadIdx.x;
    const size_t base = (size_t)blockIdx.x * ROW_ELEMS;
    const float* xg = x + base;

    for (int i = tid; i < 289; i += 384) {
        int u = i / 17, v = i - u * 17;
        w1s[u * 18 + v] = tm_w1[i];
        w2s[u * 18 + v] = tm_w2[i];
    }
    if (tid < 17) { b1s[tid] = tm_b1[tid]; b2s[tid] = tm_b2[tid]; }
    __syncthreads();

    const int d = tid;
    float xr[17];
    #pragma unroll
    for (int v = 0; v < VV; v++) xr[v] = xg[v * DD + d];
    ull xp[8];
    #pragma unroll
    for (int p = 0; p < 8; p++) xp[p] = pack2(xr[2 * p], xr[2 * p + 1]);

    float h[17];
    #pragma unroll
    for (int u = 0; u < VV; u++) {
        ull a2 = 0ull;
        const float* wr = w1s + u * 18;
        #pragma unroll
        for (int p = 0; p < 8; p++) ffma2(a2, xp[p], *(const ull*)(wr + 2 * p));
        float2 s = unpack2(a2);
        h[u] = gelu_exact(s.x + s.y + xr[16] * wr[16] + b1s[u]);
    }
    ull hp[8];
    #pragma unroll
    for (int p = 0; p < 8; p++) hp[p] = pack2(h[2 * p], h[2 * p + 1]);

    float* oc = g_xc + (size_t)blockIdx.x * VV * DD + d;
    #pragma unroll
    for (int u = 0; u < VV; u++) {
        ull a2 = 0ull;
        const float* wr = w2s + u * 18;
        #pragma unroll
        for (int p = 0; p < 8; p++) ffma2(a2, hp[p], *(const ull*)(wr + 2 * p));
        float2 s = unpack2(a2);
        oc[(size_t)u * DD] = s.x + s.y + h[16] * wr[16] + b2s[u];
    }
}

// ==================== K1b: rmsnorm(xa) -> bf16, 128 threads ====================
extern "C" __global__ void __launch_bounds__(128, 8)
k1_xa(const float* __restrict__ x, const float* __restrict__ na_w)
{
    const int warp = threadIdx.x >> 5, lane = threadIdx.x & 31;
    const float* xg = x + (size_t)blockIdx.x * ROW_ELEMS + DM;
    for (int r = warp; r < VV; r += 4) {
        float vals[4]; float s = 0.f;
        #pragma unroll
        for (int q = 0; q < 4; q++) {
            float t = xg[r * DD + lane + 32 * q];
            vals[q] = t; s += t * t;
        }
        #pragma unroll
        for (int o = 16; o; o >>= 1) s += __shfl_xor_sync(0xffffffffu, s, o);
        float rms = rsqrtf(s * (1.0f / DA) + 1e-6f);
        __nv_bfloat16* oa = g_xa + ((size_t)blockIdx.x * VV + r) * DA;
        #pragma unroll
        for (int q = 0; q < 4; q++) {
            int c = lane + 32 * q;
            oa[c] = __float2bfloat16(vals[q] * rms * na_w[c]);
        }
    }
}

// ==================== K_att2: scores + softmax + o ====================
#define QLD 388
extern "C" __global__ void __launch_bounds__(128)
k_att2()
{
    __shared__ float qkv_s[VV * QLD];
    __shared__ float sc[NH * VV * VV];

    const int tid = threadIdx.x;
    const size_t bid = blockIdx.x;

    {
        const float* src = g_qkv + bid * (VV * 384);
        #pragma unroll 4
        for (int i = tid; i < VV * 96; i += 128) {
            int v = i / 96, c = i - v * 96;
            *(float4*)(qkv_s + v * QLD + c * 4) = *(const float4*)(src + v * 384 + c * 4);
        }
    }
    __syncthreads();

    // scores (float4 LDS)
    for (int k = tid; k < NH * VV * VV; k += 128) {
        int h = k / (VV * VV), r = k - h * VV * VV, qv = r / VV, kv = r - qv * VV;
        const float4* qp = (const float4*)(qkv_s + qv * QLD + h * HD);
        const float4* kp = (const float4*)(qkv_s + kv * QLD + DA + h * HD);
        float s = 0.f;
        #pragma unroll
        for (int d = 0; d < 8; d++) {
            float4 a = qp[d], b = kp[d];
            s += a.x * b.x + a.y * b.y + a.z * b.z + a.w * b.w;
        }
        sc[k] = s * 0.17677669529663687f;
    }
    __syncthreads();

    for (int r = tid; r < NH * VV; r += 128) {
        float* row = sc + r * VV;
        float m = row[0];
        #pragma unroll
        for (int i = 1; i < VV; i++) m = fmaxf(m, row[i]);
        float s = 0.f;
        #pragma unroll
        for (int i = 0; i < VV; i++) { float e = __expf(row[i] - m); row[i] = e; s += e; }
        float inv = 1.f / s;
        #pragma unroll
        for (int i = 0; i < VV; i++) row[i] *= inv;
    }
    __syncthreads();

    {
        const int dd = tid, h = dd >> 5;
        __nv_bfloat16* og = g_o + bid * (VV * DA) + dd;
        #pragma unroll
        for (int vq = 0; vq < VV; vq++) {
            const float* arow = sc + (h * VV + vq) * VV;
            float acc = 0.f;
            #pragma unroll
            for (int kv = 0; kv < VV; kv++)
                acc += arow[kv] * qkv_s[kv * QLD + 2 * DA + dd];
            og[(size_t)vq * DA] = __float2bfloat16(acc);
        }
    }
}

// ==================== K_norm ====================
extern "C" __global__ void __launch_bounds__(256)
k_norm(const float* __restrict__ nf_w)
{
    const int warp = threadIdx.x >> 5, lane = threadIdx.x & 31;
    const size_t row = (size_t)blockIdx.x * 8 + warp;
    const float* src = g_xc + row * DD;
    float4 v[4]; float s = 0.f;
    #pragma unroll
    for (int q = 0; q < 4; q++) {
        v[q] = *(const float4*)(src + (lane + 32 * q) * 4);
        s += v[q].x * v[q].x + v[q].y * v[q].y + v[q].z * v[q].z + v[q].w * v[q].w;
    }
    #pragma unroll
    for (int o = 16; o; o >>= 1) s += __shfl_xor_sync(0xffffffffu, s, o);
    float r = rsqrtf(s * (1.0f / DD) + 1e-6f);
    __nv_bfloat16* dst = g_xn + row * DD;
    #pragma unroll
    for (int q = 0; q < 4; q++) {
        int c = (lane + 32 * q) * 4;
        const float4 wv = *(const float4*)(nf_w + c);
        __nv_bfloat162 p0 = __floats2bfloat162_rn(v[q].x * r * wv.x, v[q].y * r * wv.y);
        __nv_bfloat162 p1 = __floats2bfloat162_rn(v[q].z * r * wv.z, v[q].w * r * wv.w);
        *reinterpret_cast<__nv_bfloat162*>(dst + c)     = p0;
        *reinterpret_cast<__nv_bfloat162*>(dst + c + 2) = p1;
    }
}

// ============================ BF16 GEMM (mma.sync, round-8 engine) ============================
__device__ __forceinline__ void ldsm4(unsigned* r, unsigned addr) {
    asm volatile("ldmatrix.sync.aligned.m8n8.x4.shared.b16 {%0,%1,%2,%3}, [%4];"
        : "=r"(r[0]), "=r"(r[1]), "=r"(r[2]), "=r"(r[3]) : "r"(addr));
}
__device__ __forceinline__ void mma16816(float* c, const unsigned* a, const unsigned* b) {
    asm volatile("mma.sync.aligned.m16n8k16.row.col.f32.bf16.bf16.f32 "
        "{%0,%1,%2,%3}, {%4,%5,%6,%7}, {%8,%9}, {%0,%1,%2,%3};"
        : "+f"(c[0]), "+f"(c[1]), "+f"(c[2]), "+f"(c[3])
        : "r"(a[0]), "r"(a[1]), "r"(a[2]), "r"(a[3]), "r"(b[0]), "r"(b[1]));
}

#define KC 64
#define SRG 72
#define TILE_B ((unsigned)(128 * SRG * 2))
#define STAGE_B (2u * TILE_B)
#define GSMEM_BYTES (3 * 2 * 128 * SRG * 2)

// EPI: 1 = gelu(+bias) -> bf16 ldc 1024; 2 = +bias+resid -> f32 ldc 512 (guarded)
//      3 = +bias -> f32 ldc 384;        4 = +bias -> f32 ldc 512 (guarded, pre-offset)
template<int KTOT, int EPI>
__global__ void __launch_bounds__(256, 2)
gemm_bf16(const __nv_bfloat16* __restrict__ A,
          const __nv_bfloat16* __restrict__ B,
          const float* __restrict__ bias,
          const float* __restrict__ resid,
          __nv_bfloat16* __restrict__ Cb,
          float* __restrict__ Cf)
{
    constexpr int NT = KTOT / KC;
    extern __shared__ __nv_bfloat16 gsm[];

    const int tid  = threadIdx.x;
    const int lane = tid & 31, wid = tid >> 5;
    const int wm   = wid & 1, wn = wid >> 1;
    const int m_blk = blockIdx.y * 128, n_blk = blockIdx.x * 128;
    const unsigned sbase = (unsigned)__cvta_generic_to_shared(gsm);

    float acc[4][4][4];
    #pragma unroll
    for (int a = 0; a < 4; a++)
        #pragma unroll
        for (int b = 0; b < 4; b++)
            #pragma unroll
            for (int c = 0; c < 4; c++) acc[a][b][c] = 0.f;

    auto load_tile = [&](int st, int k0) {
        const unsigned sa = sbase + st * STAGE_B;
        const unsigned sb = sa + TILE_B;
        #pragma unroll
        for (int i = tid; i < 1024; i += 256) {
            int r = i >> 3, c = i & 7;
            unsigned off = (unsigned)(r * SRG + c * 8) * 2;
            cp_async16(sa + off, A + (size_t)(m_blk + r) * KTOT + k0 + c * 8);
            cp_async16(sb + off, B + (size_t)(n_blk + r) * KTOT + k0 + c * 8);
        }
        cp_commit();
    };

    load_tile(0, 0);
    if (NT > 1) load_tile(1, KC);

    #pragma unroll 1
    for (int t = 0; t < NT; t++) {
        if (t + 1 < NT) cp_wait1(); else cp_wait0();
        __syncthreads();
        if (t + 2 < NT) load_tile((t + 2) % 3, (t + 2) * KC);

        const unsigned sa = sbase + (t % 3) * STAGE_B;
        const unsigned sb = sa + TILE_B;

        unsigned ra[2][4][4], rb[2][2][4];
        auto ldf = [&](int ks, int pb) {
            #pragma unroll
            for (int mt = 0; mt < 4; mt++)
                ldsm4(ra[pb][mt], sa + (unsigned)((wm * 64 + mt * 16 + (lane & 15)) * SRG +
                                                  ks + (lane >> 4) * 8) * 2);
            #pragma unroll
            for (int q = 0; q < 2; q++)
                ldsm4(rb[pb][q], sb + (unsigned)((wn * 32 + q * 16 + (lane & 15)) * SRG +
                                                 ks + (lane >> 4) * 8) * 2);
        };

        ldf(0, 0);
        #pragma unroll
        for (int ksi = 0; ksi < KC / 16; ksi++) {
            if (ksi + 1 < KC / 16) ldf((ksi + 1) * 16, (ksi + 1) & 1);
            const int pb = ksi & 1;
            #pragma unroll
            for (int mt = 0; mt < 4; mt++)
                #pragma unroll
                for (int nt = 0; nt < 4; nt++) {
                    unsigned bfrag[2] = { rb[pb][nt >> 1][nt & 1],
                                          rb[pb][nt >> 1][(nt & 1) + 2] };
                    mma16816(acc[mt][nt], ra[pb][mt], bfrag);
                }
        }
    }

    const int tr = lane >> 2, tc = (lane & 3) * 2;
    #pragma unroll
    for (int mt = 0; mt < 4; mt++) {
        #pragma unroll
        for (int nt = 0; nt < 4; nt++) {
            int col = n_blk + wn * 32 + nt * 8 + tc;
            float b0 = bias[col], b1 = bias[col + 1];
            #pragma unroll
            for (int h = 0; h < 2; h++) {
                int row = m_blk + wm * 64 + mt * 16 + tr + h * 8;
                float v0 = acc[mt][nt][h * 2 + 0] + b0;
                float v1 = acc[mt][nt][h * 2 + 1] + b1;
                if (EPI == 1) {
                    __nv_bfloat162 p = __floats2bfloat162_rn(gelu_exact(v0), gelu_exact(v1));
                    *reinterpret_cast<__nv_bfloat162*>(Cb + (size_t)row * 1024 + col) = p;
                } else if (EPI == 2) {
                    if (row < MROWS) {
                        const float2 rx = *reinterpret_cast<const float2*>(resid + (size_t)row * 512 + col);
                        float2 o; o.x = v0 + rx.x; o.y = v1 + rx.y;
                        *reinterpret_cast<float2*>(Cf + (size_t)row * 512 + col) = o;
                    }
                } else if (EPI == 3) {
                    float2 o; o.x = v0; o.y = v1;
                    *reinterpret_cast<float2*>(Cf + (size_t)row * 384 + col) = o;
                } else {
                    if (row < MROWS) {
                        float2 o; o.x = v0; o.y = v1;
                        *reinterpret_cast<float2*>(Cf + (size_t)row * 512 + col) = o;
                    }
                }
            }
        }
    }
}

// ============================ LAUNCH ============================
extern "C" void kernel_launch(void* const* d_in, const int* in_sizes, int n_in,
                              void* d_out, int out_size)
{
    const float* x     = (const float*)d_in[0];
    const float* tm_w1 = (const float*)d_in[1];
    const float* tm_b1 = (const float*)d_in[2];
    const float* tm_w2 = (const float*)d_in[3];
    const float* tm_b2 = (const float*)d_in[4];
    const float* na_w  = (const float*)d_in[5];
    const float* in_w  = (const float*)d_in[6];
    const float* in_b  = (const float*)d_in[7];
    const float* out_w = (const float*)d_in[8];
    const float* out_b = (const float*)d_in[9];
    const float* nf_w  = (const float*)d_in[10];
    const float* cm_w1 = (const float*)d_in[11];
    const float* cm_b1 = (const float*)d_in[12];
    const float* cm_w2 = (const float*)d_in[13];
    const float* cm_b2 = (const float*)d_in[14];
    float* out = (float*)d_out;

    static bool init_done = false;
    static cudaStream_t s2;
    static cudaEvent_t evFork, evJoin;
    if (!init_done) {
        cudaFuncSetAttribute(gemm_bf16<512, 1>,
                             cudaFuncAttributeMaxDynamicSharedMemorySize, GSMEM_BYTES);
        cudaFuncSetAttribute(gemm_bf16<1024, 2>,
                             cudaFuncAttributeMaxDynamicSharedMemorySize, GSMEM_BYTES);
        cudaFuncSetAttribute(gemm_bf16<128, 3>,
                             cudaFuncAttributeMaxDynamicSharedMemorySize, GSMEM_BYTES);
        cudaFuncSetAttribute(gemm_bf16<128, 4>,
                             cudaFuncAttributeMaxDynamicSharedMemorySize, GSMEM_BYTES);
        cudaStreamCreateWithFlags(&s2, cudaStreamNonBlocking);
        cudaEventCreateWithFlags(&evFork, cudaEventDisableTiming);
        cudaEventCreateWithFlags(&evJoin, cudaEventDisableTiming);
        init_done = true;
    }

    __nv_bfloat16 *p_xn, *p_h, *p_w1, *p_w2, *p_xa, *p_o, *p_wqb, *p_wob;
    float *p_qkv, *p_xc;
    cudaGetSymbolAddress((void**)&p_xn,  g_xn);
    cudaGetSymbolAddress((void**)&p_h,   g_h);
    cudaGetSymbolAddress((void**)&p_w1,  g_w1);
    cudaGetSymbolAddress((void**)&p_w2,  g_w2);
    cudaGetSymbolAddress((void**)&p_xa,  g_xa);
    cudaGetSymbolAddress((void**)&p_o,   g_o);
    cudaGetSymbolAddress((void**)&p_wqb, g_wqb);
    cudaGetSymbolAddress((void**)&p_wob, g_wob);
    cudaGetSymbolAddress((void**)&p_qkv, g_qkv);
    cudaGetSymbolAddress((void**)&p_xc,  g_xc);

    // main stream: weight convert (needed by gq/go/g1/g2)
    convert_weights<<<2048, 256>>>(cm_w1, cm_w2, in_w, out_w);

    // fork: token mixer branch on s2 (independent of attention chain)
    cudaEventRecord(evFork, 0);
    cudaStreamWaitEvent(s2, evFork, 0);
    k1_mix<<<BT, 384, 0, s2>>>(x, tm_w1, tm_b1, tm_w2, tm_b2);
    cudaEventRecord(evJoin, s2);

    // main stream: attention chain
    k1_xa<<<BT, 128>>>(x, na_w);
    dim3 gq(3, MPADT);
    gemm_bf16<128, 3><<<gq, 256, GSMEM_BYTES>>>(p_xa, p_wqb, in_b, nullptr, nullptr, p_qkv);
    k_att2<<<BT, 128>>>();
    dim3 go(1, MPADT);
    gemm_bf16<128, 4><<<go, 256, GSMEM_BYTES>>>(p_o, p_wob, out_b, nullptr, nullptr, p_xc + DM);

    // join: k_norm needs both g_xc halves
    cudaStreamWaitEvent(0, evJoin, 0);
    k_norm<<<MROWS / 8, 256>>>(nf_w);

    dim3 g1(8, MPADT), g2(4, MPADT);
    gemm_bf16<512, 1><<<g1, 256, GSMEM_BYTES>>>(p_xn, p_w1, cm_b1, nullptr, p_h, nullptr);
    gemm_bf16<1024, 2><<<g2, 256, GSMEM_BYTES>>>(p_h, p_w2, cm_b2, x, nullptr, out);
}